// round 4
// baseline (speedup 1.0000x reference)
#include <cuda_runtime.h>
#include <math.h>
#include <stdint.h>

#define Bb   16
#define Nn   512
#define Dd   512
#define Hh   8
#define HDm  64
#define MR   (Bb*Nn)     // 8192 rows
#define DFF  2048

// ---------------- scratch (static device globals; no allocation) ----------------
__device__ float g_h1 [MR*Dd];
__device__ float g_QKVb[2*MR*Dd];    // [2][B][H][N][HD]  (Q, K)
__device__ float g_VT [MR*Dd];       // [B][H][HD][N]     (V transposed)
__device__ float g_S  [Bb*Hh*Nn*Nn];
__device__ float g_O  [MR*Dd];       // (B,N,D)
__device__ float g_x1 [MR*Dd];
__device__ float g_h2 [MR*Dd];
__device__ float g_mid[MR*DFF];
__device__ float g_WqkvT[3*Dd*Dd];   // [1536][512] K-major, rounded
__device__ float g_WoT [Dd*Dd];      // [512][512]
__device__ float g_W1T [DFF*Dd];     // [2048][512]
__device__ float g_W2T [Dd*DFF];     // [512][2048]
__device__ float g_bqkv[3*Dd];
__device__ int   g_adj_is32;

// ======================= helpers =======================
__device__ __forceinline__ uint32_t smem_u32(const void* p) {
    uint32_t a;
    asm("{ .reg .u64 t; cvta.to.shared.u64 t, %1; cvt.u32.u64 %0, t; }" : "=r"(a) : "l"(p));
    return a;
}
__device__ __forceinline__ float f2tf32f(float f) {
    uint32_t u; asm("cvt.rna.tf32.f32 %0, %1;" : "=r"(u) : "f"(f));
    return __uint_as_float(u);
}
__device__ __forceinline__ void cp16(const float* s, const float* g) {
    uint32_t sa = smem_u32(s);
    asm volatile("cp.async.cg.shared.global [%0], [%1], 16;" :: "r"(sa), "l"(g) : "memory");
}
#define CP_COMMIT() asm volatile("cp.async.commit_group;" ::: "memory")
#define CP_WAIT(n)  asm volatile("cp.async.wait_group %0;" :: "n"(n) : "memory")

// m16n8k8 tf32 mma, row.col
__device__ __forceinline__ void mma8(float* c, const uint32_t* a, uint32_t b0, uint32_t b1) {
    asm volatile("mma.sync.aligned.m16n8k8.row.col.f32.tf32.tf32.f32 "
        "{%0,%1,%2,%3},{%4,%5,%6,%7},{%8,%9},{%0,%1,%2,%3};"
        : "+f"(c[0]), "+f"(c[1]), "+f"(c[2]), "+f"(c[3])
        : "r"(a[0]), "r"(a[1]), "r"(a[2]), "r"(a[3]), "r"(b0), "r"(b1));
}
__device__ __forceinline__ void load8(float* d, const float* p) {
    float4 t0 = *reinterpret_cast<const float4*>(p);
    float4 t1 = *reinterpret_cast<const float4*>(p + 4);
    d[0]=t0.x; d[1]=t0.y; d[2]=t0.z; d[3]=t0.w;
    d[4]=t1.x; d[5]=t1.y; d[6]=t1.z; d[7]=t1.w;
}
#define FU(x) __float_as_uint(x)

// 32-K-chunk compute: A tile [rows][stride] at pA (warp-offset applied),
// B tile K-major [n][stride] at pB (warp-offset applied).
// k-permutation: mma step ks contracts k = 8*lr + ks (slot0) and 8*lr+ks+4 (slot1).
template<int STRIDE>
__device__ __forceinline__ void chunk_mma(const float* pA, const float* pB,
                                          float acc[2][8][4], int lq, int lr)
{
    float Ar[2][2][8];
    #pragma unroll
    for (int mt = 0; mt < 2; mt++) {
        int r = mt * 16 + lq;
        load8(Ar[mt][0], pA + r * STRIDE + 8 * lr);
        load8(Ar[mt][1], pA + (r + 8) * STRIDE + 8 * lr);
    }
    #pragma unroll
    for (int nt = 0; nt < 8; nt++) {
        float Br[8];
        load8(Br, pB + (nt * 8 + lq) * STRIDE + 8 * lr);
        #pragma unroll
        for (int ks = 0; ks < 4; ks++) {
            uint32_t af0[4] = {FU(Ar[0][0][ks]), FU(Ar[0][1][ks]), FU(Ar[0][0][ks+4]), FU(Ar[0][1][ks+4])};
            uint32_t af1[4] = {FU(Ar[1][0][ks]), FU(Ar[1][1][ks]), FU(Ar[1][0][ks+4]), FU(Ar[1][1][ks+4])};
            mma8(acc[0][nt], af0, FU(Br[ks]), FU(Br[ks+4]));
            mma8(acc[1][nt], af1, FU(Br[ks]), FU(Br[ks+4]));
        }
    }
}

// ======================= dense GEMM: C[M x ncols] = A @ Wt^T, tf32 mma ==========
// CTA 128x128, 8 warps (4M x 2N), warp 32x64, KC=32 double-buffered cp.async.
// Wt is [ncols][K] K-major (pre-rounded, pre-transposed).
// MODE 0: QKV scatter (+bias, tf32-round; V goes transposed to g_VT)
// MODE 1: +bias +res    MODE 2: gelu(+bias), round    MODE 3: (+bias+res)*mask[r]
#define DENSE_SMEM (4*4608*4)

template<int MODE>
__global__ void __launch_bounds__(256, 1) mma_gemm(
    const float* __restrict__ A, const float* __restrict__ Wt,
    const float* __restrict__ bias, const float* __restrict__ res,
    const float* __restrict__ mask, float* __restrict__ C,
    int K, int ncols)
{
    extern __shared__ float sm[];
    float* sA = sm;                  // [2][128][36]
    float* sB = sm + 2*4608;         // [2][128][36]
    const int tid = threadIdx.x, lane = tid & 31, warp = tid >> 5;
    const int wm = warp >> 1, wn = warp & 1, lq = lane >> 2, lr = lane & 3;
    const int bm = blockIdx.y * 128, bn = blockIdx.x * 128;

    float acc[2][8][4];
    #pragma unroll
    for (int i = 0; i < 2; i++)
        #pragma unroll
        for (int j = 0; j < 8; j++)
            #pragma unroll
            for (int l = 0; l < 4; l++) acc[i][j][l] = 0.0f;

    const int NC = K >> 5;

    #pragma unroll
    for (int pre = 0; pre < 2; pre++) {
        int k0 = pre * 32;
        float* dA = sA + pre * 4608;
        float* dB = sB + pre * 4608;
        #pragma unroll
        for (int i = 0; i < 4; i++) {
            int cc = tid + i * 256, row = cc >> 3, seg = cc & 7;
            cp16(dA + row*36 + seg*4, A  + (size_t)(bm + row) * K + k0 + seg*4);
        }
        #pragma unroll
        for (int i = 0; i < 4; i++) {
            int cc = tid + i * 256, row = cc >> 3, seg = cc & 7;
            cp16(dB + row*36 + seg*4, Wt + (size_t)(bn + row) * K + k0 + seg*4);
        }
        CP_COMMIT();
    }

    for (int c = 0; c < NC; c++) {
        CP_WAIT(1);
        __syncthreads();
        const float* pA = sA + (c & 1) * 4608 + (wm * 32) * 36;
        const float* pB = sB + (c & 1) * 4608 + (wn * 64) * 36;
        chunk_mma<36>(pA, pB, acc, lq, lr);
        __syncthreads();
        if (c + 2 < NC) {
            int k0 = (c + 2) * 32;
            float* dA = sA + (c & 1) * 4608;
            float* dB = sB + (c & 1) * 4608;
            #pragma unroll
            for (int i = 0; i < 4; i++) {
                int cc = tid + i * 256, row = cc >> 3, seg = cc & 7;
                cp16(dA + row*36 + seg*4, A  + (size_t)(bm + row) * K + k0 + seg*4);
            }
            #pragma unroll
            for (int i = 0; i < 4; i++) {
                int cc = tid + i * 256, row = cc >> 3, seg = cc & 7;
                cp16(dB + row*36 + seg*4, Wt + (size_t)(bn + row) * K + k0 + seg*4);
            }
        }
        CP_COMMIT();
    }

    // ---------------- epilogue ----------------
    #pragma unroll
    for (int mt = 0; mt < 2; mt++) {
        #pragma unroll
        for (int half = 0; half < 2; half++) {
            int r = bm + wm*32 + mt*16 + lq + half*8;
            float mr = (MODE == 3) ? mask[r] : 0.0f;
            #pragma unroll
            for (int nt = 0; nt < 8; nt++) {
                int cg = bn + wn*64 + nt*8 + 2*lr;
                float v0 = acc[mt][nt][half*2 + 0] + bias[cg];
                float v1 = acc[mt][nt][half*2 + 1] + bias[cg + 1];
                if (MODE == 0) {
                    int mat = cg >> 9, cc = cg & 511, hh = cc >> 6, d0 = cc & 63;
                    int b = r >> 9, n = r & 511;
                    if (mat < 2) {
                        float* op = C + (((size_t)(mat*Bb + b)*Hh + hh)*Nn + n)*HDm + d0;
                        float2 o; o.x = f2tf32f(v0); o.y = f2tf32f(v1);
                        *reinterpret_cast<float2*>(op) = o;
                    } else {
                        float* vp = g_VT + (((size_t)(b*Hh + hh))*HDm + d0)*Nn + n;
                        vp[0]  = f2tf32f(v0);
                        vp[Nn] = f2tf32f(v1);
                    }
                } else if (MODE == 1) {
                    const float* rp = res + (size_t)r * ncols + cg;
                    float2 r2 = *reinterpret_cast<const float2*>(rp);
                    float2 o; o.x = v0 + r2.x; o.y = v1 + r2.y;
                    *reinterpret_cast<float2*>(C + (size_t)r * ncols + cg) = o;
                } else if (MODE == 2) {
                    float2 o;
                    o.x = f2tf32f(0.5f * v0 * (1.0f + erff(v0 * 0.70710678118654752f)));
                    o.y = f2tf32f(0.5f * v1 * (1.0f + erff(v1 * 0.70710678118654752f)));
                    *reinterpret_cast<float2*>(C + (size_t)r * ncols + cg) = o;
                } else {
                    const float* rp = res + (size_t)r * ncols + cg;
                    float2 r2 = *reinterpret_cast<const float2*>(rp);
                    float2 o; o.x = (v0 + r2.x) * mr; o.y = (v1 + r2.y) * mr;
                    *reinterpret_cast<float2*>(C + (size_t)r * ncols + cg) = o;
                }
            }
        }
    }
}

// ======================= score: S = Q@K^T/8 + edge_bias, masked (tf32 mma) ======
#define SCORE_SMEM (2*128*68*4)
__global__ void __launch_bounds__(256, 1) score_mma(
    const float* __restrict__ Q, const float* __restrict__ Kt,
    const float* __restrict__ ebias, const int* __restrict__ adj32,
    const float* __restrict__ mask, float* __restrict__ S)
{
    extern __shared__ float sm[];
    float* sQ = sm;              // [128][68]
    float* sK = sm + 128*68;     // [128][68]
    const int tid = threadIdx.x, lane = tid & 31, warp = tid >> 5;
    const int wm = warp >> 1, wn = warp & 1, lq = lane >> 2, lr = lane & 3;
    const int bh = blockIdx.z, b = bh >> 3, h = bh & 7;
    const int qt = blockIdx.y * 128, kt = blockIdx.x * 128;

    #pragma unroll
    for (int i = 0; i < 8; i++) {
        int cc = tid + i * 256, row = cc >> 4, seg = cc & 15;
        cp16(sQ + row*68 + seg*4, Q  + (size_t)(bh*Nn + qt + row)*HDm + seg*4);
    }
    #pragma unroll
    for (int i = 0; i < 8; i++) {
        int cc = tid + i * 256, row = cc >> 4, seg = cc & 15;
        cp16(sK + row*68 + seg*4, Kt + (size_t)(bh*Nn + kt + row)*HDm + seg*4);
    }
    CP_COMMIT();
    CP_WAIT(0);
    __syncthreads();

    float acc[2][8][4];
    #pragma unroll
    for (int i = 0; i < 2; i++)
        #pragma unroll
        for (int j = 0; j < 8; j++)
            #pragma unroll
            for (int l = 0; l < 4; l++) acc[i][j][l] = 0.0f;

    #pragma unroll
    for (int kc = 0; kc < 2; kc++) {
        const float* pQ = sQ + (wm * 32) * 68 + kc * 32;
        const float* pK = sK + (wn * 64) * 68 + kc * 32;
        chunk_mma<68>(pQ, pK, acc, lq, lr);
    }

    const int is32 = g_adj_is32;
    #pragma unroll
    for (int mt = 0; mt < 2; mt++) {
        #pragma unroll
        for (int half = 0; half < 2; half++) {
            int q = qt + wm*32 + mt*16 + lq + half*8;
            float mq = mask[b*Nn + q];
            int arow = (b*Nn + q) * Nn;
            #pragma unroll
            for (int nt = 0; nt < 8; nt++) {
                int k = kt + wn*64 + nt*8 + 2*lr;
                int t0 = is32 ? adj32[arow + k]     : adj32[2*(arow + k)];
                int t1 = is32 ? adj32[arow + k + 1] : adj32[2*(arow + k + 1)];
                float s0 = acc[mt][nt][half*2 + 0] * 0.125f + ebias[t0*Hh + h];
                float s1 = acc[mt][nt][half*2 + 1] * 0.125f + ebias[t1*Hh + h];
                if (mq * mask[b*Nn + k]     == 0.0f) s0 = -1e30f;
                if (mq * mask[b*Nn + k + 1] == 0.0f) s1 = -1e30f;
                float2 o; o.x = s0; o.y = s1;
                *reinterpret_cast<float2*>(S + (size_t)(bh*Nn + q)*Nn + k) = o;
            }
        }
    }
}

// ======================= PV: O = P@V (tf32 mma), V^T K-major =====================
#define PV_SMEM ((2*9216 + 2*2304)*4)
__global__ void __launch_bounds__(256, 1) pv_mma(
    const float* __restrict__ S, const float* __restrict__ VT, float* __restrict__ O)
{
    extern __shared__ float sm[];
    float* sP = sm;                 // [2][256][36]
    float* sV = sm + 2*9216;        // [2][64][36]   (rows = hd, cols = seq chunk)
    const int tid = threadIdx.x, lane = tid & 31, warp = tid >> 5;
    const int lq = lane >> 2, lr = lane & 3;
    const int bh = blockIdx.y, b = bh >> 3, h = bh & 7;
    const int qt = blockIdx.x * 256;

    float acc[2][8][4];
    #pragma unroll
    for (int i = 0; i < 2; i++)
        #pragma unroll
        for (int j = 0; j < 8; j++)
            #pragma unroll
            for (int l = 0; l < 4; l++) acc[i][j][l] = 0.0f;

    #pragma unroll
    for (int pre = 0; pre < 2; pre++) {
        int k0 = pre * 32;
        float* dP = sP + pre * 9216;
        float* dV = sV + pre * 2304;
        #pragma unroll
        for (int i = 0; i < 8; i++) {
            int cc = tid + i * 256, row = cc >> 3, seg = cc & 7;
            cp16(dP + row*36 + seg*4, S  + (size_t)(bh*Nn + qt + row)*Nn + k0 + seg*4);
        }
        #pragma unroll
        for (int i = 0; i < 2; i++) {
            int cc = tid + i * 256, row = cc >> 3, seg = cc & 7;
            cp16(dV + row*36 + seg*4, VT + (size_t)(bh*HDm + row)*Nn + k0 + seg*4);
        }
        CP_COMMIT();
    }

    for (int c = 0; c < 16; c++) {
        CP_WAIT(1);
        __syncthreads();
        const float* pP = sP + (c & 1) * 9216 + (warp * 32) * 36;
        const float* pV = sV + (c & 1) * 2304;
        chunk_mma<36>(pP, pV, acc, lq, lr);
        __syncthreads();
        if (c + 2 < 16) {
            int k0 = (c + 2) * 32;
            float* dP = sP + (c & 1) * 9216;
            float* dV = sV + (c & 1) * 2304;
            #pragma unroll
            for (int i = 0; i < 8; i++) {
                int cc = tid + i * 256, row = cc >> 3, seg = cc & 7;
                cp16(dP + row*36 + seg*4, S  + (size_t)(bh*Nn + qt + row)*Nn + k0 + seg*4);
            }
            #pragma unroll
            for (int i = 0; i < 2; i++) {
                int cc = tid + i * 256, row = cc >> 3, seg = cc & 7;
                cp16(dV + row*36 + seg*4, VT + (size_t)(bh*HDm + row)*Nn + k0 + seg*4);
            }
        }
        CP_COMMIT();
    }

    #pragma unroll
    for (int mt = 0; mt < 2; mt++) {
        #pragma unroll
        for (int half = 0; half < 2; half++) {
            int q = qt + warp*32 + mt*16 + lq + half*8;
            #pragma unroll
            for (int nt = 0; nt < 8; nt++) {
                int d = nt*8 + 2*lr;
                float2 o;
                o.x = f2tf32f(acc[mt][nt][half*2 + 0]);
                o.y = f2tf32f(acc[mt][nt][half*2 + 1]);
                *reinterpret_cast<float2*>(O + (size_t)(b*Nn + q)*Dd + h*HDm + d) = o;
            }
        }
    }
}

// ---------------- weight round + transpose: out[n*R + k] = round(in[k*C + n]) ----
__global__ void round_tr(const float* __restrict__ in, float* __restrict__ out,
                         int R, int C)
{
    __shared__ float t[32][33];
    int bx = blockIdx.x * 32, by = blockIdx.y * 32;
    int x = bx + threadIdx.x;
    #pragma unroll
    for (int i = 0; i < 32; i += 8)
        t[threadIdx.y + i][threadIdx.x] = in[(size_t)(by + threadIdx.y + i) * C + x];
    __syncthreads();
    int xo = by + threadIdx.x;
    #pragma unroll
    for (int i = 0; i < 32; i += 8)
        out[(size_t)(bx + threadIdx.y + i) * R + xo] = f2tf32f(t[threadIdx.x][threadIdx.y + i]);
}

__global__ void concat_bias_kernel(const float* __restrict__ a, const float* __restrict__ b,
                                   const float* __restrict__ c, float* __restrict__ o)
{
    int i = blockIdx.x * 256 + threadIdx.x;
    if (i < 512) o[i] = a[i];
    else if (i < 1024) o[i] = b[i - 512];
    else o[i] = c[i - 1024];
}

// ---------------- adj dtype detection (int32 vs int64) ----------------
__global__ void detect_adj_kernel(const int* __restrict__ a) {
    __shared__ int flag;
    if (threadIdx.x == 0) flag = 0;
    __syncthreads();
    for (int i = threadIdx.x; i < 8192; i += blockDim.x)
        if (a[2*i + 1] != 0) flag = 1;
    __syncthreads();
    if (threadIdx.x == 0) g_adj_is32 = flag;
}

// ---------------- LayerNorm (output tf32-rounded: feeds mma A operand) ----------
__global__ __launch_bounds__(256) void ln_kernel(
    const float* __restrict__ X, const float* __restrict__ g,
    const float* __restrict__ beta, float* __restrict__ Y)
{
    int row = blockIdx.x;
    const float* x = X + (size_t)row * Dd;
    int tid = threadIdx.x;
    float v0 = x[tid], v1 = x[tid + 256];

    __shared__ float red1[8], red2[8];
    float s = v0 + v1;
    #pragma unroll
    for (int o = 16; o; o >>= 1) s += __shfl_xor_sync(0xffffffffu, s, o);
    if ((tid & 31) == 0) red1[tid >> 5] = s;
    __syncthreads();
    float tot = red1[0]+red1[1]+red1[2]+red1[3]+red1[4]+red1[5]+red1[6]+red1[7];
    float mu = tot * (1.0f / 512.0f);

    float d0 = v0 - mu, d1 = v1 - mu;
    float s2 = d0*d0 + d1*d1;
    #pragma unroll
    for (int o = 16; o; o >>= 1) s2 += __shfl_xor_sync(0xffffffffu, s2, o);
    if ((tid & 31) == 0) red2[tid >> 5] = s2;
    __syncthreads();
    float tot2 = red2[0]+red2[1]+red2[2]+red2[3]+red2[4]+red2[5]+red2[6]+red2[7];
    float inv = rsqrtf(tot2 * (1.0f / 512.0f) + 1e-5f);

    Y[(size_t)row*Dd + tid      ] = f2tf32f(d0 * inv * g[tid      ] + beta[tid      ]);
    Y[(size_t)row*Dd + tid + 256] = f2tf32f(d1 * inv * g[tid + 256] + beta[tid + 256]);
}

// ---------------- softmax (in place on S, output tf32-rounded) ----------------
__global__ __launch_bounds__(256) void softmax_kernel(float* __restrict__ S)
{
    int warp = threadIdx.x >> 5, lane = threadIdx.x & 31;
    int row = blockIdx.x * 8 + warp;
    float* p = S + (size_t)row * Nn;
    float v[16];
    float mx = -3e30f;
    #pragma unroll
    for (int i = 0; i < 16; i++) { v[i] = p[i * 32 + lane]; mx = fmaxf(mx, v[i]); }
    #pragma unroll
    for (int o = 16; o; o >>= 1) mx = fmaxf(mx, __shfl_xor_sync(0xffffffffu, mx, o));
    if (mx < -1e29f) {
        #pragma unroll
        for (int i = 0; i < 16; i++) p[i * 32 + lane] = 0.0f;
        return;
    }
    float s = 0.0f;
    #pragma unroll
    for (int i = 0; i < 16; i++) { v[i] = expf(v[i] - mx); s += v[i]; }
    #pragma unroll
    for (int o = 16; o; o >>= 1) s += __shfl_xor_sync(0xffffffffu, s, o);
    float inv = 1.0f / s;
    #pragma unroll
    for (int i = 0; i < 16; i++) p[i * 32 + lane] = f2tf32f(v[i] * inv);
}

// ---------------------------------- launch ----------------------------------
extern "C" void kernel_launch(void* const* d_in, const int* in_sizes, int n_in,
                              void* d_out, int out_size)
{
    const float* x    = (const float*)d_in[0];
    const int*   adj  = (const int*)  d_in[1];
    const float* mask = (const float*)d_in[2];
    const float* Wq   = (const float*)d_in[3];
    const float* bq   = (const float*)d_in[4];
    const float* Wk   = (const float*)d_in[5];
    const float* bk   = (const float*)d_in[6];
    const float* Wv   = (const float*)d_in[7];
    const float* bv   = (const float*)d_in[8];
    const float* Wo   = (const float*)d_in[9];
    const float* bo   = (const float*)d_in[10];
    const float* eb   = (const float*)d_in[11];
    const float* W1   = (const float*)d_in[12];
    const float* b1   = (const float*)d_in[13];
    const float* W2   = (const float*)d_in[14];
    const float* b2   = (const float*)d_in[15];
    const float* g1   = (const float*)d_in[16];
    const float* be1  = (const float*)d_in[17];
    const float* g2   = (const float*)d_in[18];
    const float* be2  = (const float*)d_in[19];
    float* out = (float*)d_out;

    float *h1, *QKVb, *VT, *S, *O, *x1, *h2, *mid;
    float *WqkvT, *WoT, *W1T, *W2T, *bqkv;
    cudaGetSymbolAddress((void**)&h1,   g_h1);
    cudaGetSymbolAddress((void**)&QKVb, g_QKVb);
    cudaGetSymbolAddress((void**)&VT,   g_VT);
    cudaGetSymbolAddress((void**)&S,    g_S);
    cudaGetSymbolAddress((void**)&O,    g_O);
    cudaGetSymbolAddress((void**)&x1,   g_x1);
    cudaGetSymbolAddress((void**)&h2,   g_h2);
    cudaGetSymbolAddress((void**)&mid,  g_mid);
    cudaGetSymbolAddress((void**)&WqkvT,g_WqkvT);
    cudaGetSymbolAddress((void**)&WoT,  g_WoT);
    cudaGetSymbolAddress((void**)&W1T,  g_W1T);
    cudaGetSymbolAddress((void**)&W2T,  g_W2T);
    cudaGetSymbolAddress((void**)&bqkv, g_bqkv);

    static int attr_set = 0;
    if (!attr_set) {
        cudaFuncSetAttribute(mma_gemm<0>, cudaFuncAttributeMaxDynamicSharedMemorySize, DENSE_SMEM);
        cudaFuncSetAttribute(mma_gemm<1>, cudaFuncAttributeMaxDynamicSharedMemorySize, DENSE_SMEM);
        cudaFuncSetAttribute(mma_gemm<2>, cudaFuncAttributeMaxDynamicSharedMemorySize, DENSE_SMEM);
        cudaFuncSetAttribute(mma_gemm<3>, cudaFuncAttributeMaxDynamicSharedMemorySize, DENSE_SMEM);
        cudaFuncSetAttribute(score_mma,   cudaFuncAttributeMaxDynamicSharedMemorySize, SCORE_SMEM);
        cudaFuncSetAttribute(pv_mma,      cudaFuncAttributeMaxDynamicSharedMemorySize, PV_SMEM);
        attr_set = 1;
    }

    detect_adj_kernel<<<1, 256>>>(adj);

    // weights: round to tf32 + transpose to [n][k]
    dim3 tb(32, 8);
    round_tr<<<dim3(16, 16), tb>>>(Wq, WqkvT + 0*Dd*Dd, Dd, Dd);
    round_tr<<<dim3(16, 16), tb>>>(Wk, WqkvT + 1*Dd*Dd, Dd, Dd);
    round_tr<<<dim3(16, 16), tb>>>(Wv, WqkvT + 2*Dd*Dd, Dd, Dd);
    round_tr<<<dim3(16, 16), tb>>>(Wo, WoT, Dd, Dd);
    round_tr<<<dim3(64, 16), tb>>>(W1, W1T, Dd, DFF);
    round_tr<<<dim3(16, 64), tb>>>(W2, W2T, DFF, Dd);
    concat_bias_kernel<<<6, 256>>>(bq, bk, bv, bqkv);

    // LN1 (tf32-rounded out)
    ln_kernel<<<MR, 256>>>(x, g1, be1, h1);
    // fused QKV: [8192 x 512] @ [512 x 1536] -> Q,K head layout, V transposed
    mma_gemm<0><<<dim3(12, 64), 256, DENSE_SMEM>>>(h1, WqkvT, bqkv, nullptr, nullptr, QKVb, Dd, 3*Dd);
    const float* Qp = QKVb;
    const float* Kp = QKVb + (size_t)MR * Dd;
    // scores + edge bias + mask
    score_mma<<<dim3(4, 4, Bb * Hh), 256, SCORE_SMEM>>>(Qp, Kp, eb, adj, mask, S);
    softmax_kernel<<<(Bb * Hh * Nn) / 8, 256>>>(S);
    pv_mma<<<dim3(2, Bb * Hh), 256, PV_SMEM>>>(S, VT, O);
    // output projection + residual
    mma_gemm<1><<<dim3(4, 64), 256, DENSE_SMEM>>>(O, WoT, bo, x, nullptr, x1, Dd, Dd);
    // LN2
    ln_kernel<<<MR, 256>>>(x1, g2, be2, h2);
    // FFN1 + exact gelu (tf32-rounded out)
    mma_gemm<2><<<dim3(16, 64), 256, DENSE_SMEM>>>(h2, W1T, b1, nullptr, nullptr, mid, Dd, DFF);
    // FFN2 + residual + final mask
    mma_gemm<3><<<dim3(4, 64), 256, DENSE_SMEM>>>(mid, W2T, b2, x1, mask, out, DFF, Dd);
}

// round 5
// speedup vs baseline: 2.1779x; 2.1779x over previous
#include <cuda_runtime.h>
#include <cuda_fp16.h>
#include <math.h>
#include <stdint.h>

#define Bb   16
#define Nn   512
#define Dd   512
#define Hh   8
#define HDm  64
#define MR   (Bb*Nn)
#define DFF  2048

// ---------------- scratch (static device globals) ----------------
__device__ __half g_h1 [MR*Dd];
__device__ __half g_QKh[2*MR*Dd];     // [2][B][H][N][HD]
__device__ __half g_Vh [MR*Dd];       // [B][H][N][HD]
__device__ __half g_VTh[MR*Dd];       // [B][H][HD][N]
__device__ __half g_S  [(size_t)Bb*Hh*Nn*Nn];
__device__ __half g_O  [MR*Dd];       // (B,N,D) half
__device__ float  g_x1 [MR*Dd];
__device__ __half g_h2 [MR*Dd];
__device__ __half g_mid[MR*DFF];
__device__ __half g_Wqkvh[3*Dd*Dd];   // [1536][512] K-major
__device__ __half g_WoTh [Dd*Dd];
__device__ __half g_W1Th [DFF*Dd];
__device__ __half g_W2Th [Dd*DFF];
__device__ float  g_bqkv[3*Dd];
__device__ int    g_adj_is32;

// ======================= helpers =======================
__device__ __forceinline__ uint32_t smem_u32(const void* p) {
    uint32_t a;
    asm("{ .reg .u64 t; cvta.to.shared.u64 t, %1; cvt.u32.u64 %0, t; }" : "=r"(a) : "l"(p));
    return a;
}
__device__ __forceinline__ void cp16h(void* s, const __half* g) {
    uint32_t sa = smem_u32(s);
    asm volatile("cp.async.cg.shared.global [%0], [%1], 16;" :: "r"(sa), "l"(g) : "memory");
}
#define CP_COMMIT() asm volatile("cp.async.commit_group;" ::: "memory")
#define CP_WAIT(n)  asm volatile("cp.async.wait_group %0;" :: "n"(n) : "memory")

__device__ __forceinline__ int swz3(int r) {          // bit-reverse of r&7
    return ((r & 1) << 2) | (r & 2) | ((r & 4) >> 2);
}

// m16n8k16 fp16 mma, f32 accum, row.col
__device__ __forceinline__ void mma16(float* c, uint32_t a0, uint32_t a1, uint32_t a2,
                                      uint32_t a3, uint32_t b0, uint32_t b1) {
    asm volatile("mma.sync.aligned.m16n8k16.row.col.f32.f16.f16.f32 "
        "{%0,%1,%2,%3},{%4,%5,%6,%7},{%8,%9},{%0,%1,%2,%3};"
        : "+f"(c[0]), "+f"(c[1]), "+f"(c[2]), "+f"(c[3])
        : "r"(a0), "r"(a1), "r"(a2), "r"(a3), "r"(b0), "r"(b1));
}

// warp 32x64 tile compute over one 64-k plane pair (A rows at pa, B rows at pb)
__device__ __forceinline__ void plane_mma(const char* pa, const char* pb,
                                          float acc[2][8][4], int lq, int lr, int sl)
{
    #pragma unroll
    for (int sc = 0; sc < 2; sc++) {
        int go = ((sc * 4 + lr) ^ sl) << 4;
        uint4 Ar[2][2];
        #pragma unroll
        for (int mt = 0; mt < 2; mt++) {
            Ar[mt][0] = *reinterpret_cast<const uint4*>(pa + (mt*16 + lq    ) * 128 + go);
            Ar[mt][1] = *reinterpret_cast<const uint4*>(pa + (mt*16 + lq + 8) * 128 + go);
        }
        #pragma unroll
        for (int nt = 0; nt < 8; nt++) {
            uint4 Bv = *reinterpret_cast<const uint4*>(pb + (nt*8 + lq) * 128 + go);
            mma16(acc[0][nt], Ar[0][0].x, Ar[0][1].x, Ar[0][0].y, Ar[0][1].y, Bv.x, Bv.y);
            mma16(acc[1][nt], Ar[1][0].x, Ar[1][1].x, Ar[1][0].y, Ar[1][1].y, Bv.x, Bv.y);
            mma16(acc[0][nt], Ar[0][0].z, Ar[0][1].z, Ar[0][0].w, Ar[0][1].w, Bv.z, Bv.w);
            mma16(acc[1][nt], Ar[1][0].z, Ar[1][1].z, Ar[1][0].w, Ar[1][1].w, Bv.z, Bv.w);
        }
    }
}

// ======================= dense GEMM: C = A[Mx K] @ Wt[ncols x K]^T ==============
// CTA 128x128, 8 warps (4Mx2N), K chunks of 64, double-buffered cp.async.
// MODE 0: QKV scatter to head layouts (Q,K -> Cv, V -> g_Vh), +bias, half out
// MODE 1: float out = acc + bias + res
// MODE 2: half out = gelu_exact(acc + bias)
// MODE 3: float out = (acc + bias + res) * mask[row]
#define DENSE_SMEM 65536

template<int MODE>
__global__ void __launch_bounds__(256, 2) hgemm(
    const __half* __restrict__ A, const __half* __restrict__ Wt,
    const float* __restrict__ bias, const float* __restrict__ res,
    const float* __restrict__ mask, void* Cv, int K, int ncols)
{
    extern __shared__ char sm[];
    const int tid = threadIdx.x, lane = tid & 31, warp = tid >> 5;
    const int wm = warp >> 1, wn = warp & 1, lq = lane >> 2, lr = lane & 3;
    const int bm = blockIdx.y * 128, bn = blockIdx.x * 128;
    const int sl = swz3(lq);

    float acc[2][8][4];
    #pragma unroll
    for (int i = 0; i < 2; i++)
        #pragma unroll
        for (int j = 0; j < 8; j++)
            #pragma unroll
            for (int l = 0; l < 4; l++) acc[i][j][l] = 0.0f;

    const int NC = K >> 6;

    auto loadc = [&](int c, int buf) {
        char* dA = sm + buf * 32768;
        char* dB = dA + 16384;
        int k0 = c << 6;
        #pragma unroll
        for (int i = 0; i < 4; i++) {
            int idx = tid + i * 256, row = idx >> 3, g = idx & 7;
            int gp = ((g ^ swz3(row & 7)) << 4);
            cp16h(dA + row * 128 + gp, A  + (size_t)(bm + row) * K + k0 + g * 8);
            cp16h(dB + row * 128 + gp, Wt + (size_t)(bn + row) * K + k0 + g * 8);
        }
    };
    loadc(0, 0); CP_COMMIT();
    loadc(1, 1); CP_COMMIT();

    for (int c = 0; c < NC; c++) {
        CP_WAIT(1);
        __syncthreads();
        const char* pa = sm + (c & 1) * 32768 + (wm * 32) * 128;
        const char* pb = sm + (c & 1) * 32768 + 16384 + (wn * 64) * 128;
        plane_mma(pa, pb, acc, lq, lr, sl);
        __syncthreads();
        if (c + 2 < NC) loadc(c + 2, c & 1);
        CP_COMMIT();
    }

    // ---------------- epilogue ----------------
    #pragma unroll
    for (int mt = 0; mt < 2; mt++) {
        #pragma unroll
        for (int hf = 0; hf < 2; hf++) {
            int r = bm + wm*32 + mt*16 + lq + hf*8;
            float mr = (MODE == 3) ? mask[r] : 0.0f;
            #pragma unroll
            for (int nt = 0; nt < 8; nt++) {
                int cg = bn + wn*64 + nt*8 + 2*lr;
                float v0 = acc[mt][nt][hf*2 + 0] + bias[cg];
                float v1 = acc[mt][nt][hf*2 + 1] + bias[cg + 1];
                if (MODE == 0) {
                    int mat = cg >> 9, cc = cg & 511, hh = cc >> 6, d0 = cc & 63;
                    int b = r >> 9, n = r & 511;
                    __half2 hv = __floats2half2_rn(v0, v1);
                    if (mat < 2) {
                        __half* op = (__half*)Cv + ((((size_t)mat*Bb + b)*Hh + hh)*Nn + n)*HDm + d0;
                        *reinterpret_cast<__half2*>(op) = hv;
                    } else {
                        __half* vp = g_Vh + (((size_t)b*Hh + hh)*Nn + n)*HDm + d0;
                        *reinterpret_cast<__half2*>(vp) = hv;
                    }
                } else if (MODE == 1) {
                    float* C = (float*)Cv;
                    const float* rp = res + (size_t)r * ncols + cg;
                    float2 r2 = *reinterpret_cast<const float2*>(rp);
                    float2 o; o.x = v0 + r2.x; o.y = v1 + r2.y;
                    *reinterpret_cast<float2*>(C + (size_t)r * ncols + cg) = o;
                } else if (MODE == 2) {
                    __half* C = (__half*)Cv;
                    float o0 = 0.5f * v0 * (1.0f + erff(v0 * 0.70710678118654752f));
                    float o1 = 0.5f * v1 * (1.0f + erff(v1 * 0.70710678118654752f));
                    *reinterpret_cast<__half2*>(C + (size_t)r * ncols + cg) = __floats2half2_rn(o0, o1);
                } else {
                    float* C = (float*)Cv;
                    const float* rp = res + (size_t)r * ncols + cg;
                    float2 r2 = *reinterpret_cast<const float2*>(rp);
                    float2 o; o.x = (v0 + r2.x) * mr; o.y = (v1 + r2.y) * mr;
                    *reinterpret_cast<float2*>(C + (size_t)r * ncols + cg) = o;
                }
            }
        }
    }
}

// ======================= score: S = Q@K^T/8 + edge_bias, masked, half out =======
#define SCORE_SMEM 32768
__global__ void __launch_bounds__(256, 2) score_mma(
    const __half* __restrict__ Q, const __half* __restrict__ Kh,
    const float* __restrict__ ebias, const int* __restrict__ adj32,
    const float* __restrict__ mask, __half* __restrict__ S)
{
    extern __shared__ char sm[];
    char* sQ = sm;            // 128 rows x 128B
    char* sK = sm + 16384;
    const int tid = threadIdx.x, lane = tid & 31, warp = tid >> 5;
    const int wm = warp >> 1, wn = warp & 1, lq = lane >> 2, lr = lane & 3;
    const int bh = blockIdx.z, b = bh >> 3, h = bh & 7;
    const int qt = blockIdx.y * 128, kt = blockIdx.x * 128;
    const int sl = swz3(lq);

    #pragma unroll
    for (int i = 0; i < 4; i++) {
        int idx = tid + i * 256, row = idx >> 3, g = idx & 7;
        int gp = ((g ^ swz3(row & 7)) << 4);
        cp16h(sQ + row * 128 + gp, Q  + (size_t)(bh*Nn + qt + row) * HDm + g * 8);
        cp16h(sK + row * 128 + gp, Kh + (size_t)(bh*Nn + kt + row) * HDm + g * 8);
    }
    CP_COMMIT();
    CP_WAIT(0);
    __syncthreads();

    float acc[2][8][4];
    #pragma unroll
    for (int i = 0; i < 2; i++)
        #pragma unroll
        for (int j = 0; j < 8; j++)
            #pragma unroll
            for (int l = 0; l < 4; l++) acc[i][j][l] = 0.0f;

    plane_mma(sQ + (wm*32)*128, sK + (wn*64)*128, acc, lq, lr, sl);

    const int is32 = g_adj_is32;
    #pragma unroll
    for (int mt = 0; mt < 2; mt++) {
        #pragma unroll
        for (int hf = 0; hf < 2; hf++) {
            int q = qt + wm*32 + mt*16 + lq + hf*8;
            float mq = mask[b*Nn + q];
            int arow = (b*Nn + q) * Nn;
            #pragma unroll
            for (int nt = 0; nt < 8; nt++) {
                int k = kt + wn*64 + nt*8 + 2*lr;
                int t0 = is32 ? adj32[arow + k]     : adj32[2*(arow + k)];
                int t1 = is32 ? adj32[arow + k + 1] : adj32[2*(arow + k + 1)];
                float s0 = acc[mt][nt][hf*2 + 0] * 0.125f + ebias[t0*Hh + h];
                float s1 = acc[mt][nt][hf*2 + 1] * 0.125f + ebias[t1*Hh + h];
                if (mq * mask[b*Nn + k]     == 0.0f) s0 = -60000.0f;
                if (mq * mask[b*Nn + k + 1] == 0.0f) s1 = -60000.0f;
                *reinterpret_cast<__half2*>(S + (size_t)(bh*Nn + q)*Nn + k) = __floats2half2_rn(s0, s1);
            }
        }
    }
}

// ======================= PV: O = P@V, half, V^T K-major ==========================
#define PV_SMEM 81920
__global__ void __launch_bounds__(256, 2) pv_mma(
    const __half* __restrict__ P, const __half* __restrict__ VT, __half* __restrict__ O)
{
    extern __shared__ char sm[];
    // sP: 2 bufs x 256 rows x 128B at 0/32768; sV: 2 bufs x 64 rows x 128B at 65536/73728
    const int tid = threadIdx.x, lane = tid & 31, warp = tid >> 5;
    const int lq = lane >> 2, lr = lane & 3;
    const int bh = blockIdx.y, b = bh >> 3, h = bh & 7;
    const int qt = blockIdx.x * 256;
    const int sl = swz3(lq);

    float acc[2][8][4];
    #pragma unroll
    for (int i = 0; i < 2; i++)
        #pragma unroll
        for (int j = 0; j < 8; j++)
            #pragma unroll
            for (int l = 0; l < 4; l++) acc[i][j][l] = 0.0f;

    auto loadc = [&](int c, int buf) {
        char* dP = sm + buf * 32768;
        char* dV = sm + 65536 + buf * 8192;
        int k0 = c << 6;
        #pragma unroll
        for (int i = 0; i < 8; i++) {
            int idx = tid + i * 256, row = idx >> 3, g = idx & 7;
            int gp = ((g ^ swz3(row & 7)) << 4);
            cp16h(dP + row * 128 + gp, P + (size_t)(bh*Nn + qt + row) * Nn + k0 + g * 8);
        }
        #pragma unroll
        for (int i = 0; i < 2; i++) {
            int idx = tid + i * 256, row = idx >> 3, g = idx & 7;
            int gp = ((g ^ swz3(row & 7)) << 4);
            cp16h(dV + row * 128 + gp, VT + ((size_t)bh*HDm + row) * Nn + k0 + g * 8);
        }
    };
    loadc(0, 0); CP_COMMIT();
    loadc(1, 1); CP_COMMIT();

    for (int c = 0; c < 8; c++) {
        CP_WAIT(1);
        __syncthreads();
        const char* pa = sm + (c & 1) * 32768 + (warp * 32) * 128;
        const char* pb = sm + 65536 + (c & 1) * 8192;
        plane_mma(pa, pb, acc, lq, lr, sl);
        __syncthreads();
        if (c + 2 < 8) loadc(c + 2, c & 1);
        CP_COMMIT();
    }

    #pragma unroll
    for (int mt = 0; mt < 2; mt++) {
        #pragma unroll
        for (int hf = 0; hf < 2; hf++) {
            int q = qt + warp*32 + mt*16 + lq + hf*8;
            #pragma unroll
            for (int nt = 0; nt < 8; nt++) {
                int d = nt*8 + 2*lr;
                __half2 hv = __floats2half2_rn(acc[mt][nt][hf*2+0], acc[mt][nt][hf*2+1]);
                *reinterpret_cast<__half2*>(O + ((size_t)(b*Nn + q))*Dd + h*HDm + d) = hv;
            }
        }
    }
}

// ---------------- V transpose per (b,h): [512][64] -> [64][512], half ----------
__global__ void vtrans(const __half* __restrict__ V, __half* __restrict__ VT)
{
    __shared__ __half t[64][65];
    int bh = blockIdx.y, nb = blockIdx.x * 64;
    int tx = threadIdx.x, ty = threadIdx.y;
    const __half2* src = reinterpret_cast<const __half2*>(V + ((size_t)bh*Nn + nb) * HDm);
    #pragma unroll
    for (int i = 0; i < 8; i++) {
        int n = ty + i * 8;
        __half2 v = src[n * 32 + tx];
        t[n][2*tx] = __low2half(v); t[n][2*tx+1] = __high2half(v);
    }
    __syncthreads();
    __half2* dst = reinterpret_cast<__half2*>(VT + (size_t)bh * HDm * Nn);
    #pragma unroll
    for (int i = 0; i < 8; i++) {
        int d = ty + i * 8;
        __half2 o = __halves2half2(t[2*tx][d], t[2*tx+1][d]);
        dst[(d * Nn + nb + 2*tx) >> 1] = o;
    }
}

// ---------------- weight convert: out[n][k] = half(in[k][n]) --------------------
__global__ void wcvt(const float* __restrict__ s0, const float* __restrict__ s1,
                     const float* __restrict__ s2,
                     __half* __restrict__ d0, __half* __restrict__ d1, __half* __restrict__ d2,
                     int K0, int N0, int K1, int N1, int K2, int N2)
{
    int z = blockIdx.z;
    const float* in; __half* out; int K, N;
    if (z == 0) { in = s0; out = d0; K = K0; N = N0; }
    else if (z == 1) { in = s1; out = d1; K = K1; N = N1; }
    else { in = s2; out = d2; K = K2; N = N2; }
    int bx = blockIdx.x * 32, by = blockIdx.y * 32;
    if (bx >= N || by >= K) return;
    __shared__ float t[32][33];
    int tx = threadIdx.x, ty = threadIdx.y;
    #pragma unroll
    for (int i = 0; i < 32; i += 8)
        t[ty + i][tx] = in[(size_t)(by + ty + i) * N + bx + tx];
    __syncthreads();
    #pragma unroll
    for (int i = 0; i < 32; i += 8)
        out[(size_t)(bx + ty + i) * K + by + tx] = __float2half_rn(t[tx][ty + i]);
}

__global__ void concat_bias_kernel(const float* __restrict__ a, const float* __restrict__ b,
                                   const float* __restrict__ c, float* __restrict__ o)
{
    int i = blockIdx.x * 256 + threadIdx.x;
    if (i < 512) o[i] = a[i];
    else if (i < 1024) o[i] = b[i - 512];
    else o[i] = c[i - 1024];
}

__global__ void detect_adj_kernel(const int* __restrict__ a) {
    __shared__ int flag;
    if (threadIdx.x == 0) flag = 0;
    __syncthreads();
    for (int i = threadIdx.x; i < 8192; i += blockDim.x)
        if (a[2*i + 1] != 0) flag = 1;
    __syncthreads();
    if (threadIdx.x == 0) g_adj_is32 = flag;
}

// ---------------- LayerNorm: fp32 in, half out ----------------
__global__ __launch_bounds__(256) void ln_kernel(
    const float* __restrict__ X, const float* __restrict__ g,
    const float* __restrict__ beta, __half* __restrict__ Y)
{
    int row = blockIdx.x;
    const float* x = X + (size_t)row * Dd;
    int tid = threadIdx.x;
    float v0 = x[tid], v1 = x[tid + 256];

    __shared__ float red1[8], red2[8];
    float s = v0 + v1;
    #pragma unroll
    for (int o = 16; o; o >>= 1) s += __shfl_xor_sync(0xffffffffu, s, o);
    if ((tid & 31) == 0) red1[tid >> 5] = s;
    __syncthreads();
    float tot = red1[0]+red1[1]+red1[2]+red1[3]+red1[4]+red1[5]+red1[6]+red1[7];
    float mu = tot * (1.0f / 512.0f);

    float d0 = v0 - mu, d1 = v1 - mu;
    float s2 = d0*d0 + d1*d1;
    #pragma unroll
    for (int o = 16; o; o >>= 1) s2 += __shfl_xor_sync(0xffffffffu, s2, o);
    if ((tid & 31) == 0) red2[tid >> 5] = s2;
    __syncthreads();
    float tot2 = red2[0]+red2[1]+red2[2]+red2[3]+red2[4]+red2[5]+red2[6]+red2[7];
    float inv = rsqrtf(tot2 * (1.0f / 512.0f) + 1e-5f);

    Y[(size_t)row*Dd + tid      ] = __float2half_rn(d0 * inv * g[tid      ] + beta[tid      ]);
    Y[(size_t)row*Dd + tid + 256] = __float2half_rn(d1 * inv * g[tid + 256] + beta[tid + 256]);
}

// ---------------- softmax on half S, in place; masked rows -> 0 ----------------
__global__ __launch_bounds__(256) void softmax_h(__half* __restrict__ S)
{
    int warp = threadIdx.x >> 5, lane = threadIdx.x & 31;
    size_t row = (size_t)blockIdx.x * 8 + warp;
    uint4* p = reinterpret_cast<uint4*>(S + row * Nn);
    uint4 u0 = p[lane], u1 = p[lane + 32];
    float v[16];
    {
        const __half2* h0 = reinterpret_cast<const __half2*>(&u0);
        const __half2* h1 = reinterpret_cast<const __half2*>(&u1);
        #pragma unroll
        for (int j = 0; j < 4; j++) {
            float2 f = __half22float2(h0[j]); v[2*j] = f.x; v[2*j+1] = f.y;
            float2 g = __half22float2(h1[j]); v[8+2*j] = g.x; v[8+2*j+1] = g.y;
        }
    }
    float mx = -3e30f;
    #pragma unroll
    for (int i = 0; i < 16; i++) mx = fmaxf(mx, v[i]);
    #pragma unroll
    for (int o = 16; o; o >>= 1) mx = fmaxf(mx, __shfl_xor_sync(0xffffffffu, mx, o));
    if (mx < -5.0e4f) {
        uint4 z = {0,0,0,0};
        p[lane] = z; p[lane + 32] = z;
        return;
    }
    float s = 0.0f;
    #pragma unroll
    for (int i = 0; i < 16; i++) { v[i] = expf(v[i] - mx); s += v[i]; }
    #pragma unroll
    for (int o = 16; o; o >>= 1) s += __shfl_xor_sync(0xffffffffu, s, o);
    float inv = 1.0f / s;
    uint4 o0, o1;
    {
        __half2* h0 = reinterpret_cast<__half2*>(&o0);
        __half2* h1 = reinterpret_cast<__half2*>(&o1);
        #pragma unroll
        for (int j = 0; j < 4; j++) {
            h0[j] = __floats2half2_rn(v[2*j] * inv, v[2*j+1] * inv);
            h1[j] = __floats2half2_rn(v[8+2*j] * inv, v[8+2*j+1] * inv);
        }
    }
    p[lane] = o0; p[lane + 32] = o1;
}

// ---------------------------------- launch ----------------------------------
extern "C" void kernel_launch(void* const* d_in, const int* in_sizes, int n_in,
                              void* d_out, int out_size)
{
    const float* x    = (const float*)d_in[0];
    const int*   adj  = (const int*)  d_in[1];
    const float* mask = (const float*)d_in[2];
    const float* Wq   = (const float*)d_in[3];
    const float* bq   = (const float*)d_in[4];
    const float* Wk   = (const float*)d_in[5];
    const float* bk   = (const float*)d_in[6];
    const float* Wv   = (const float*)d_in[7];
    const float* bv   = (const float*)d_in[8];
    const float* Wo   = (const float*)d_in[9];
    const float* bo   = (const float*)d_in[10];
    const float* eb   = (const float*)d_in[11];
    const float* W1   = (const float*)d_in[12];
    const float* b1   = (const float*)d_in[13];
    const float* W2   = (const float*)d_in[14];
    const float* b2   = (const float*)d_in[15];
    const float* g1   = (const float*)d_in[16];
    const float* be1  = (const float*)d_in[17];
    const float* g2   = (const float*)d_in[18];
    const float* be2  = (const float*)d_in[19];
    float* out = (float*)d_out;

    __half *h1, *QKh, *Vh, *VTh, *S, *O, *h2, *mid;
    __half *Wqkvh, *WoTh, *W1Th, *W2Th;
    float *x1, *bqkv;
    cudaGetSymbolAddress((void**)&h1,   g_h1);
    cudaGetSymbolAddress((void**)&QKh,  g_QKh);
    cudaGetSymbolAddress((void**)&Vh,   g_Vh);
    cudaGetSymbolAddress((void**)&VTh,  g_VTh);
    cudaGetSymbolAddress((void**)&S,    g_S);
    cudaGetSymbolAddress((void**)&O,    g_O);
    cudaGetSymbolAddress((void**)&x1,   g_x1);
    cudaGetSymbolAddress((void**)&h2,   g_h2);
    cudaGetSymbolAddress((void**)&mid,  g_mid);
    cudaGetSymbolAddress((void**)&Wqkvh,g_Wqkvh);
    cudaGetSymbolAddress((void**)&WoTh, g_WoTh);
    cudaGetSymbolAddress((void**)&W1Th, g_W1Th);
    cudaGetSymbolAddress((void**)&W2Th, g_W2Th);
    cudaGetSymbolAddress((void**)&bqkv, g_bqkv);

    static int attr_set = 0;
    if (!attr_set) {
        cudaFuncSetAttribute(hgemm<0>, cudaFuncAttributeMaxDynamicSharedMemorySize, DENSE_SMEM);
        cudaFuncSetAttribute(hgemm<1>, cudaFuncAttributeMaxDynamicSharedMemorySize, DENSE_SMEM);
        cudaFuncSetAttribute(hgemm<2>, cudaFuncAttributeMaxDynamicSharedMemorySize, DENSE_SMEM);
        cudaFuncSetAttribute(hgemm<3>, cudaFuncAttributeMaxDynamicSharedMemorySize, DENSE_SMEM);
        cudaFuncSetAttribute(pv_mma,   cudaFuncAttributeMaxDynamicSharedMemorySize, PV_SMEM);
        attr_set = 1;
    }

    dim3 tb(32, 8);
    // 0
    detect_adj_kernel<<<1, 256>>>(adj);
    // 1
    concat_bias_kernel<<<6, 256>>>(bq, bk, bv, bqkv);
    // 2: QKV weights -> half, K-major, packed [1536][512]
    wcvt<<<dim3(16, 16, 3), tb>>>(Wq, Wk, Wv,
        Wqkvh, Wqkvh + (size_t)Dd*Dd, Wqkvh + (size_t)2*Dd*Dd,
        Dd, Dd, Dd, Dd, Dd, Dd);
    // 3: Wo, W1, W2 -> half K-major
    wcvt<<<dim3(64, 64, 3), tb>>>(Wo, W1, W2, WoTh, W1Th, W2Th,
        Dd, Dd, Dd, DFF, DFF, Dd);
    // 4
    ln_kernel<<<MR, 256>>>(x, g1, be1, h1);
    // 5: fused QKV  (ncu -s 5 profiles this)
    hgemm<0><<<dim3(12, 64), 256, DENSE_SMEM>>>(h1, Wqkvh, bqkv, nullptr, nullptr, QKh, Dd, 3*Dd);
    // 6
    vtrans<<<dim3(8, Bb*Hh), tb>>>(Vh, VTh);
    // 7
    const __half* Qp = QKh;
    const __half* Kp = QKh + (size_t)MR * Dd;
    score_mma<<<dim3(4, 4, Bb*Hh), 256, SCORE_SMEM>>>(Qp, Kp, eb, adj, mask, S);
    // 8
    softmax_h<<<(Bb*Hh*Nn) / 8, 256>>>(S);
    // 9
    pv_mma<<<dim3(2, Bb*Hh), 256, PV_SMEM>>>(S, VTh, O);
    // 10: output projection + residual -> x1 (fp32)
    hgemm<1><<<dim3(4, 64), 256, DENSE_SMEM>>>(O, WoTh, bo, x, nullptr, x1, Dd, Dd);
    // 11
    ln_kernel<<<MR, 256>>>(x1, g2, be2, h2);
    // 12: FFN1 + exact gelu -> mid (half)
    hgemm<2><<<dim3(16, 64), 256, DENSE_SMEM>>>(h2, W1Th, b1, nullptr, nullptr, mid, Dd, DFF);
    // 13: FFN2 + residual + final mask -> out (fp32)
    hgemm<3><<<dim3(4, 64), 256, DENSE_SMEM>>>(mid, W2Th, b2, x1, mask, out, DFF, Dd);
}

// round 6
// speedup vs baseline: 2.2803x; 1.0470x over previous
#include <cuda_runtime.h>
#include <cuda_fp16.h>
#include <math.h>
#include <stdint.h>

#define Bb   16
#define Nn   512
#define Dd   512
#define Hh   8
#define HDm  64
#define MR   (Bb*Nn)
#define DFF  2048

// ---------------- scratch (static device globals) ----------------
__device__ __half g_h1 [MR*Dd];
__device__ __half g_QKh[2*MR*Dd];     // [2][B][H][N][HD]
__device__ __half g_Vh [MR*Dd];       // [B][H][N][HD]
__device__ __half g_VTh[MR*Dd];       // [B][H][HD][N]
__device__ __half g_O  [MR*Dd];       // (B,N,D) half
__device__ float  g_x1 [MR*Dd];
__device__ __half g_h2 [MR*Dd];
__device__ __half g_mid[MR*DFF];
__device__ __half g_Wqkvh[3*Dd*Dd];   // [1536][512] K-major
__device__ __half g_WoTh [Dd*Dd];
__device__ __half g_W1Th [DFF*Dd];
__device__ __half g_W2Th [Dd*DFF];
__device__ float  g_bqkv[3*Dd];
__device__ int    g_adj_is32;

// ======================= helpers =======================
__device__ __forceinline__ uint32_t smem_u32(const void* p) {
    uint32_t a;
    asm("{ .reg .u64 t; cvta.to.shared.u64 t, %1; cvt.u32.u64 %0, t; }" : "=r"(a) : "l"(p));
    return a;
}
__device__ __forceinline__ void cp16h(void* s, const __half* g) {
    uint32_t sa = smem_u32(s);
    asm volatile("cp.async.cg.shared.global [%0], [%1], 16;" :: "r"(sa), "l"(g) : "memory");
}
#define CP_COMMIT() asm volatile("cp.async.commit_group;" ::: "memory")
#define CP_WAIT(n)  asm volatile("cp.async.wait_group %0;" :: "n"(n) : "memory")

__device__ __forceinline__ int swz3(int r) {          // bit-reverse of r&7
    return ((r & 1) << 2) | (r & 2) | ((r & 4) >> 2);
}
__device__ __forceinline__ uint32_t h2u(float a, float b) {
    __half2 v = __floats2half2_rn(a, b);
    return *reinterpret_cast<uint32_t*>(&v);
}

// m16n8k16 fp16 mma, f32 accum, row.col
__device__ __forceinline__ void mma16(float* c, uint32_t a0, uint32_t a1, uint32_t a2,
                                      uint32_t a3, uint32_t b0, uint32_t b1) {
    asm volatile("mma.sync.aligned.m16n8k16.row.col.f32.f16.f16.f32 "
        "{%0,%1,%2,%3},{%4,%5,%6,%7},{%8,%9},{%0,%1,%2,%3};"
        : "+f"(c[0]), "+f"(c[1]), "+f"(c[2]), "+f"(c[3])
        : "r"(a0), "r"(a1), "r"(a2), "r"(a3), "r"(b0), "r"(b1));
}

// warp 32x64 tile compute over one 64-k plane pair (A rows at pa, B rows at pb)
__device__ __forceinline__ void plane_mma(const char* pa, const char* pb,
                                          float acc[2][8][4], int lq, int lr, int sl)
{
    #pragma unroll
    for (int sc = 0; sc < 2; sc++) {
        int go = ((sc * 4 + lr) ^ sl) << 4;
        uint4 Ar[2][2];
        #pragma unroll
        for (int mt = 0; mt < 2; mt++) {
            Ar[mt][0] = *reinterpret_cast<const uint4*>(pa + (mt*16 + lq    ) * 128 + go);
            Ar[mt][1] = *reinterpret_cast<const uint4*>(pa + (mt*16 + lq + 8) * 128 + go);
        }
        #pragma unroll
        for (int nt = 0; nt < 8; nt++) {
            uint4 Bv = *reinterpret_cast<const uint4*>(pb + (nt*8 + lq) * 128 + go);
            mma16(acc[0][nt], Ar[0][0].x, Ar[0][1].x, Ar[0][0].y, Ar[0][1].y, Bv.x, Bv.y);
            mma16(acc[1][nt], Ar[1][0].x, Ar[1][1].x, Ar[1][0].y, Ar[1][1].y, Bv.x, Bv.y);
            mma16(acc[0][nt], Ar[0][0].z, Ar[0][1].z, Ar[0][0].w, Ar[0][1].w, Bv.z, Bv.w);
            mma16(acc[1][nt], Ar[1][0].z, Ar[1][1].z, Ar[1][0].w, Ar[1][1].w, Bv.z, Bv.w);
        }
    }
}

// ======================= dense GEMM (unchanged from R5) =========================
#define DENSE_SMEM 65536

template<int MODE>
__global__ void __launch_bounds__(256, 2) hgemm(
    const __half* __restrict__ A, const __half* __restrict__ Wt,
    const float* __restrict__ bias, const float* __restrict__ res,
    const float* __restrict__ mask, void* Cv, int K, int ncols)
{
    extern __shared__ char sm[];
    const int tid = threadIdx.x, lane = tid & 31, warp = tid >> 5;
    const int wm = warp >> 1, wn = warp & 1, lq = lane >> 2, lr = lane & 3;
    const int bm = blockIdx.y * 128, bn = blockIdx.x * 128;
    const int sl = swz3(lq);

    float acc[2][8][4];
    #pragma unroll
    for (int i = 0; i < 2; i++)
        #pragma unroll
        for (int j = 0; j < 8; j++)
            #pragma unroll
            for (int l = 0; l < 4; l++) acc[i][j][l] = 0.0f;

    const int NC = K >> 6;

    auto loadc = [&](int c, int buf) {
        char* dA = sm + buf * 32768;
        char* dB = dA + 16384;
        int k0 = c << 6;
        #pragma unroll
        for (int i = 0; i < 4; i++) {
            int idx = tid + i * 256, row = idx >> 3, g = idx & 7;
            int gp = ((g ^ swz3(row & 7)) << 4);
            cp16h(dA + row * 128 + gp, A  + (size_t)(bm + row) * K + k0 + g * 8);
            cp16h(dB + row * 128 + gp, Wt + (size_t)(bn + row) * K + k0 + g * 8);
        }
    };
    loadc(0, 0); CP_COMMIT();
    loadc(1, 1); CP_COMMIT();

    for (int c = 0; c < NC; c++) {
        CP_WAIT(1);
        __syncthreads();
        const char* pa = sm + (c & 1) * 32768 + (wm * 32) * 128;
        const char* pb = sm + (c & 1) * 32768 + 16384 + (wn * 64) * 128;
        plane_mma(pa, pb, acc, lq, lr, sl);
        __syncthreads();
        if (c + 2 < NC) loadc(c + 2, c & 1);
        CP_COMMIT();
    }

    #pragma unroll
    for (int mt = 0; mt < 2; mt++) {
        #pragma unroll
        for (int hf = 0; hf < 2; hf++) {
            int r = bm + wm*32 + mt*16 + lq + hf*8;
            float mr = (MODE == 3) ? mask[r] : 0.0f;
            #pragma unroll
            for (int nt = 0; nt < 8; nt++) {
                int cg = bn + wn*64 + nt*8 + 2*lr;
                float v0 = acc[mt][nt][hf*2 + 0] + bias[cg];
                float v1 = acc[mt][nt][hf*2 + 1] + bias[cg + 1];
                if (MODE == 0) {
                    int mat = cg >> 9, cc = cg & 511, hh = cc >> 6, d0 = cc & 63;
                    int b = r >> 9, n = r & 511;
                    __half2 hv = __floats2half2_rn(v0, v1);
                    if (mat < 2) {
                        __half* op = (__half*)Cv + ((((size_t)mat*Bb + b)*Hh + hh)*Nn + n)*HDm + d0;
                        *reinterpret_cast<__half2*>(op) = hv;
                    } else {
                        __half* vp = g_Vh + (((size_t)b*Hh + hh)*Nn + n)*HDm + d0;
                        *reinterpret_cast<__half2*>(vp) = hv;
                    }
                } else if (MODE == 1) {
                    float* C = (float*)Cv;
                    const float* rp = res + (size_t)r * ncols + cg;
                    float2 r2 = *reinterpret_cast<const float2*>(rp);
                    float2 o; o.x = v0 + r2.x; o.y = v1 + r2.y;
                    *reinterpret_cast<float2*>(C + (size_t)r * ncols + cg) = o;
                } else if (MODE == 2) {
                    __half* C = (__half*)Cv;
                    float o0 = 0.5f * v0 * (1.0f + erff(v0 * 0.70710678118654752f));
                    float o1 = 0.5f * v1 * (1.0f + erff(v1 * 0.70710678118654752f));
                    *reinterpret_cast<__half2*>(C + (size_t)r * ncols + cg) = __floats2half2_rn(o0, o1);
                } else {
                    float* C = (float*)Cv;
                    const float* rp = res + (size_t)r * ncols + cg;
                    float2 r2 = *reinterpret_cast<const float2*>(rp);
                    float2 o; o.x = (v0 + r2.x) * mr; o.y = (v1 + r2.y) * mr;
                    *reinterpret_cast<float2*>(C + (size_t)r * ncols + cg) = o;
                }
            }
        }
    }
}

// ======================= fused attention: S -> softmax -> P@V ====================
// Grid: (4 q-tiles, B*H). CTA 256 thr, 8 warps x 16 q-rows. 8 k-tiles of 64,
// double-buffered K/V^T cp.async, online softmax, P stays in registers.
#define FA_SMEM 50176

__global__ void __launch_bounds__(256, 2) attn_fused(
    const __half* __restrict__ Q, const __half* __restrict__ Kh,
    const __half* __restrict__ VT, const float* __restrict__ ebias,
    const int* __restrict__ adj32, const float* __restrict__ mask,
    __half* __restrict__ O)
{
    extern __shared__ char sm[];
    char*  Qs  = sm;                          // 128 rows x 128B
    char*  Ks  = sm + 16384;                  // 2 x 64 rows x 128B
    char*  Vs  = sm + 32768;                  // 2 x 64 rows x 128B
    float* ebs = (float*)(sm + 49152);        // 40 floats
    float* kms = (float*)(sm + 49408);        // 2 x 64 floats

    const int tid = threadIdx.x, lane = tid & 31, w = tid >> 5;
    const int lq = lane >> 2, lr = lane & 3;
    const int bh = blockIdx.y, b = bh >> 3, h = bh & 7;
    const int qt = blockIdx.x * 128;
    const int sl = swz3(lq);

    // ---- prologue loads: Q + tile0 (G0), tile1 (G1) ----
    #pragma unroll
    for (int i = 0; i < 4; i++) {
        int idx = tid + i * 256, row = idx >> 3, g = idx & 7;
        cp16h(Qs + row * 128 + ((g ^ swz3(row & 7)) << 4),
              Q + ((size_t)bh * Nn + qt + row) * HDm + g * 8);
    }
    #pragma unroll
    for (int i = 0; i < 2; i++) {
        int idx = tid + i * 256, row = idx >> 3, g = idx & 7;
        int gp = ((g ^ swz3(row & 7)) << 4);
        cp16h(Ks + row * 128 + gp, Kh + ((size_t)bh * Nn + row) * HDm + g * 8);
        cp16h(Vs + row * 128 + gp, VT + ((size_t)bh * HDm + row) * Nn + g * 8);
    }
    if (tid < 40)  ebs[tid] = ebias[tid];
    if (tid < 128) kms[tid] = mask[b * Nn + tid];   // cols 0-63 -> buf0, 64-127 -> buf1
    CP_COMMIT();
    #pragma unroll
    for (int i = 0; i < 2; i++) {
        int idx = tid + i * 256, row = idx >> 3, g = idx & 7;
        int gp = ((g ^ swz3(row & 7)) << 4);
        cp16h(Ks + 8192 + row * 128 + gp, Kh + ((size_t)bh * Nn + 64 + row) * HDm + g * 8);
        cp16h(Vs + 8192 + row * 128 + gp, VT + ((size_t)bh * HDm + row) * Nn + 64 + g * 8);
    }
    CP_COMMIT();

    float Oa[8][4];
    #pragma unroll
    for (int i = 0; i < 8; i++)
        #pragma unroll
        for (int j = 0; j < 4; j++) Oa[i][j] = 0.0f;
    float m0 = -1e30f, m1 = -1e30f, l0 = 0.0f, l1 = 0.0f;

    const int q0 = qt + w * 16 + lq;
    const float mq0 = mask[b * Nn + q0];
    const float mq1 = mask[b * Nn + q0 + 8];
    const int is32 = g_adj_is32;
    const size_t arow0 = ((size_t)b * Nn + q0) * Nn;
    const size_t arow1 = arow0 + (size_t)8 * Nn;

    for (int t = 0; t < 8; t++) {
        CP_WAIT(1);
        __syncthreads();
        const char*  Kb = Ks + (t & 1) * 8192;
        const char*  Vb = Vs + (t & 1) * 8192;
        const float* km = kms + (t & 1) * 64;

        // ---- score mma: S[16 q][64 kk] per warp ----
        float Sa[8][4];
        #pragma unroll
        for (int i = 0; i < 8; i++)
            #pragma unroll
            for (int j = 0; j < 4; j++) Sa[i][j] = 0.0f;
        #pragma unroll
        for (int sc = 0; sc < 2; sc++) {
            int go = ((sc * 4 + lr) ^ sl) << 4;
            uint4 A0 = *reinterpret_cast<const uint4*>(Qs + (w*16 + lq    ) * 128 + go);
            uint4 A1 = *reinterpret_cast<const uint4*>(Qs + (w*16 + lq + 8) * 128 + go);
            #pragma unroll
            for (int nt = 0; nt < 8; nt++) {
                uint4 Bv = *reinterpret_cast<const uint4*>(Kb + (nt*8 + lq) * 128 + go);
                mma16(Sa[nt], A0.x, A1.x, A0.y, A1.y, Bv.x, Bv.y);
                mma16(Sa[nt], A0.z, A1.z, A0.w, A1.w, Bv.z, Bv.w);
            }
        }

        // ---- edge bias + mask ----
        int kbase = t * 64;
        #pragma unroll
        for (int nt = 0; nt < 8; nt++) {
            #pragma unroll
            for (int j = 0; j < 2; j++) {
                int kloc = nt * 8 + 2 * lr + j;
                int kc = kbase + kloc;
                float kmv = km[kloc];
                int t0 = is32 ? adj32[arow0 + kc] : adj32[2 * (arow0 + kc)];
                int t1 = is32 ? adj32[arow1 + kc] : adj32[2 * (arow1 + kc)];
                float s0 = Sa[nt][j]     * 0.125f + ebs[t0 * Hh + h];
                float s1 = Sa[nt][2 + j] * 0.125f + ebs[t1 * Hh + h];
                Sa[nt][j]     = (mq0 * kmv == 0.0f) ? -60000.0f : s0;
                Sa[nt][2 + j] = (mq1 * kmv == 0.0f) ? -60000.0f : s1;
            }
        }

        // ---- online softmax update ----
        float tm0 = -1e30f, tm1 = -1e30f;
        #pragma unroll
        for (int nt = 0; nt < 8; nt++) {
            tm0 = fmaxf(tm0, fmaxf(Sa[nt][0], Sa[nt][1]));
            tm1 = fmaxf(tm1, fmaxf(Sa[nt][2], Sa[nt][3]));
        }
        tm0 = fmaxf(tm0, __shfl_xor_sync(0xffffffffu, tm0, 1));
        tm0 = fmaxf(tm0, __shfl_xor_sync(0xffffffffu, tm0, 2));
        tm1 = fmaxf(tm1, __shfl_xor_sync(0xffffffffu, tm1, 1));
        tm1 = fmaxf(tm1, __shfl_xor_sync(0xffffffffu, tm1, 2));
        float nm0 = fmaxf(m0, tm0), nm1 = fmaxf(m1, tm1);
        float c0 = expf(m0 - nm0), c1 = expf(m1 - nm1);
        float rs0 = 0.0f, rs1 = 0.0f;
        #pragma unroll
        for (int nt = 0; nt < 8; nt++) {
            Sa[nt][0] = expf(Sa[nt][0] - nm0); rs0 += Sa[nt][0];
            Sa[nt][1] = expf(Sa[nt][1] - nm0); rs0 += Sa[nt][1];
            Sa[nt][2] = expf(Sa[nt][2] - nm1); rs1 += Sa[nt][2];
            Sa[nt][3] = expf(Sa[nt][3] - nm1); rs1 += Sa[nt][3];
        }
        rs0 += __shfl_xor_sync(0xffffffffu, rs0, 1);
        rs0 += __shfl_xor_sync(0xffffffffu, rs0, 2);
        rs1 += __shfl_xor_sync(0xffffffffu, rs1, 1);
        rs1 += __shfl_xor_sync(0xffffffffu, rs1, 2);
        l0 = l0 * c0 + rs0; l1 = l1 * c1 + rs1;
        m0 = nm0; m1 = nm1;
        #pragma unroll
        for (int nt = 0; nt < 8; nt++) {
            Oa[nt][0] *= c0; Oa[nt][1] *= c0;
            Oa[nt][2] *= c1; Oa[nt][3] *= c1;
        }

        // ---- P -> half fragments (C-frag == A-frag layout) ----
        uint32_t ph[8][2];
        #pragma unroll
        for (int nt = 0; nt < 8; nt++) {
            ph[nt][0] = h2u(Sa[nt][0], Sa[nt][1]);
            ph[nt][1] = h2u(Sa[nt][2], Sa[nt][3]);
        }

        // ---- PV mma: Oa[16 q][64 d] += P[16][64] @ V[64][64] ----
        #pragma unroll
        for (int kf = 0; kf < 4; kf++) {
            uint32_t a0 = ph[2*kf][0],   a1 = ph[2*kf][1];
            uint32_t a2 = ph[2*kf+1][0], a3 = ph[2*kf+1][1];
            int g0 = (((2*kf)     ^ sl) << 4) + lr * 4;
            int g1 = (((2*kf + 1) ^ sl) << 4) + lr * 4;
            #pragma unroll
            for (int nt = 0; nt < 8; nt++) {
                const char* vr = Vb + (nt*8 + lq) * 128;
                uint32_t b0 = *reinterpret_cast<const uint32_t*>(vr + g0);
                uint32_t b1 = *reinterpret_cast<const uint32_t*>(vr + g1);
                mma16(Oa[nt], a0, a1, a2, a3, b0, b1);
            }
        }

        __syncthreads();
        if (t + 2 < 8) {
            int kt2 = (t + 2) * 64;
            char* dK = Ks + (t & 1) * 8192;
            char* dV = Vs + (t & 1) * 8192;
            #pragma unroll
            for (int i = 0; i < 2; i++) {
                int idx = tid + i * 256, row = idx >> 3, g = idx & 7;
                int gp = ((g ^ swz3(row & 7)) << 4);
                cp16h(dK + row * 128 + gp, Kh + ((size_t)bh * Nn + kt2 + row) * HDm + g * 8);
                cp16h(dV + row * 128 + gp, VT + ((size_t)bh * HDm + row) * Nn + kt2 + g * 8);
            }
            if (tid < 64) kms[(t & 1) * 64 + tid] = mask[b * Nn + kt2 + tid];
        }
        CP_COMMIT();
    }

    // ---- normalize + write O (B,N,D) half ----
    float inv0 = (m0 > -5.0e4f) ? (1.0f / l0) : 0.0f;
    float inv1 = (m1 > -5.0e4f) ? (1.0f / l1) : 0.0f;
    __half* o0 = O + ((size_t)(b * Nn + q0)) * Dd + h * HDm;
    __half* o1 = o0 + (size_t)8 * Dd;
    #pragma unroll
    for (int nt = 0; nt < 8; nt++) {
        int d = nt * 8 + 2 * lr;
        *reinterpret_cast<__half2*>(o0 + d) = __floats2half2_rn(Oa[nt][0] * inv0, Oa[nt][1] * inv0);
        *reinterpret_cast<__half2*>(o1 + d) = __floats2half2_rn(Oa[nt][2] * inv1, Oa[nt][3] * inv1);
    }
}

// ---------------- V transpose per (b,h): [512][64] -> [64][512], half ----------
__global__ void vtrans(const __half* __restrict__ V, __half* __restrict__ VT)
{
    __shared__ __half t[64][65];
    int bh = blockIdx.y, nb = blockIdx.x * 64;
    int tx = threadIdx.x, ty = threadIdx.y;
    const __half2* src = reinterpret_cast<const __half2*>(V + ((size_t)bh*Nn + nb) * HDm);
    #pragma unroll
    for (int i = 0; i < 8; i++) {
        int n = ty + i * 8;
        __half2 v = src[n * 32 + tx];
        t[n][2*tx] = __low2half(v); t[n][2*tx+1] = __high2half(v);
    }
    __syncthreads();
    __half2* dst = reinterpret_cast<__half2*>(VT + (size_t)bh * HDm * Nn);
    #pragma unroll
    for (int i = 0; i < 8; i++) {
        int d = ty + i * 8;
        __half2 o = __halves2half2(t[2*tx][d], t[2*tx+1][d]);
        dst[(d * Nn + nb + 2*tx) >> 1] = o;
    }
}

// ---------------- weight convert: out[n][k] = half(in[k][n]) --------------------
__global__ void wcvt(const float* __restrict__ s0, const float* __restrict__ s1,
                     const float* __restrict__ s2,
                     __half* __restrict__ d0, __half* __restrict__ d1, __half* __restrict__ d2,
                     int K0, int N0, int K1, int N1, int K2, int N2)
{
    int z = blockIdx.z;
    const float* in; __half* out; int K, N;
    if (z == 0) { in = s0; out = d0; K = K0; N = N0; }
    else if (z == 1) { in = s1; out = d1; K = K1; N = N1; }
    else { in = s2; out = d2; K = K2; N = N2; }
    int bx = blockIdx.x * 32, by = blockIdx.y * 32;
    if (bx >= N || by >= K) return;
    __shared__ float t[32][33];
    int tx = threadIdx.x, ty = threadIdx.y;
    #pragma unroll
    for (int i = 0; i < 32; i += 8)
        t[ty + i][tx] = in[(size_t)(by + ty + i) * N + bx + tx];
    __syncthreads();
    #pragma unroll
    for (int i = 0; i < 32; i += 8)
        out[(size_t)(bx + ty + i) * K + by + tx] = __float2half_rn(t[tx][ty + i]);
}

__global__ void concat_bias_kernel(const float* __restrict__ a, const float* __restrict__ b,
                                   const float* __restrict__ c, float* __restrict__ o)
{
    int i = blockIdx.x * 256 + threadIdx.x;
    if (i < 512) o[i] = a[i];
    else if (i < 1024) o[i] = b[i - 512];
    else o[i] = c[i - 1024];
}

__global__ void detect_adj_kernel(const int* __restrict__ a) {
    __shared__ int flag;
    if (threadIdx.x == 0) flag = 0;
    __syncthreads();
    for (int i = threadIdx.x; i < 8192; i += blockDim.x)
        if (a[2*i + 1] != 0) flag = 1;
    __syncthreads();
    if (threadIdx.x == 0) g_adj_is32 = flag;
}

// ---------------- LayerNorm: fp32 in, half out ----------------
__global__ __launch_bounds__(256) void ln_kernel(
    const float* __restrict__ X, const float* __restrict__ g,
    const float* __restrict__ beta, __half* __restrict__ Y)
{
    int row = blockIdx.x;
    const float* x = X + (size_t)row * Dd;
    int tid = threadIdx.x;
    float v0 = x[tid], v1 = x[tid + 256];

    __shared__ float red1[8], red2[8];
    float s = v0 + v1;
    #pragma unroll
    for (int o = 16; o; o >>= 1) s += __shfl_xor_sync(0xffffffffu, s, o);
    if ((tid & 31) == 0) red1[tid >> 5] = s;
    __syncthreads();
    float tot = red1[0]+red1[1]+red1[2]+red1[3]+red1[4]+red1[5]+red1[6]+red1[7];
    float mu = tot * (1.0f / 512.0f);

    float d0 = v0 - mu, d1 = v1 - mu;
    float s2 = d0*d0 + d1*d1;
    #pragma unroll
    for (int o = 16; o; o >>= 1) s2 += __shfl_xor_sync(0xffffffffu, s2, o);
    if ((tid & 31) == 0) red2[tid >> 5] = s2;
    __syncthreads();
    float tot2 = red2[0]+red2[1]+red2[2]+red2[3]+red2[4]+red2[5]+red2[6]+red2[7];
    float inv = rsqrtf(tot2 * (1.0f / 512.0f) + 1e-5f);

    Y[(size_t)row*Dd + tid      ] = __float2half_rn(d0 * inv * g[tid      ] + beta[tid      ]);
    Y[(size_t)row*Dd + tid + 256] = __float2half_rn(d1 * inv * g[tid + 256] + beta[tid + 256]);
}

// ---------------------------------- launch ----------------------------------
extern "C" void kernel_launch(void* const* d_in, const int* in_sizes, int n_in,
                              void* d_out, int out_size)
{
    const float* x    = (const float*)d_in[0];
    const int*   adj  = (const int*)  d_in[1];
    const float* mask = (const float*)d_in[2];
    const float* Wq   = (const float*)d_in[3];
    const float* bq   = (const float*)d_in[4];
    const float* Wk   = (const float*)d_in[5];
    const float* bk   = (const float*)d_in[6];
    const float* Wv   = (const float*)d_in[7];
    const float* bv   = (const float*)d_in[8];
    const float* Wo   = (const float*)d_in[9];
    const float* bo   = (const float*)d_in[10];
    const float* eb   = (const float*)d_in[11];
    const float* W1   = (const float*)d_in[12];
    const float* b1   = (const float*)d_in[13];
    const float* W2   = (const float*)d_in[14];
    const float* b2   = (const float*)d_in[15];
    const float* g1   = (const float*)d_in[16];
    const float* be1  = (const float*)d_in[17];
    const float* g2   = (const float*)d_in[18];
    const float* be2  = (const float*)d_in[19];
    float* out = (float*)d_out;

    __half *h1, *QKh, *Vh, *VTh, *O, *h2, *mid;
    __half *Wqkvh, *WoTh, *W1Th, *W2Th;
    float *x1, *bqkv;
    cudaGetSymbolAddress((void**)&h1,   g_h1);
    cudaGetSymbolAddress((void**)&QKh,  g_QKh);
    cudaGetSymbolAddress((void**)&Vh,   g_Vh);
    cudaGetSymbolAddress((void**)&VTh,  g_VTh);
    cudaGetSymbolAddress((void**)&O,    g_O);
    cudaGetSymbolAddress((void**)&x1,   g_x1);
    cudaGetSymbolAddress((void**)&h2,   g_h2);
    cudaGetSymbolAddress((void**)&mid,  g_mid);
    cudaGetSymbolAddress((void**)&Wqkvh,g_Wqkvh);
    cudaGetSymbolAddress((void**)&WoTh, g_WoTh);
    cudaGetSymbolAddress((void**)&W1Th, g_W1Th);
    cudaGetSymbolAddress((void**)&W2Th, g_W2Th);
    cudaGetSymbolAddress((void**)&bqkv, g_bqkv);

    static int attr_set = 0;
    if (!attr_set) {
        cudaFuncSetAttribute(hgemm<0>, cudaFuncAttributeMaxDynamicSharedMemorySize, DENSE_SMEM);
        cudaFuncSetAttribute(hgemm<1>, cudaFuncAttributeMaxDynamicSharedMemorySize, DENSE_SMEM);
        cudaFuncSetAttribute(hgemm<2>, cudaFuncAttributeMaxDynamicSharedMemorySize, DENSE_SMEM);
        cudaFuncSetAttribute(hgemm<3>, cudaFuncAttributeMaxDynamicSharedMemorySize, DENSE_SMEM);
        cudaFuncSetAttribute(attn_fused, cudaFuncAttributeMaxDynamicSharedMemorySize, FA_SMEM);
        attr_set = 1;
    }

    dim3 tb(32, 8);
    detect_adj_kernel<<<1, 256>>>(adj);
    concat_bias_kernel<<<6, 256>>>(bq, bk, bv, bqkv);
    wcvt<<<dim3(16, 16, 3), tb>>>(Wq, Wk, Wv,
        Wqkvh, Wqkvh + (size_t)Dd*Dd, Wqkvh + (size_t)2*Dd*Dd,
        Dd, Dd, Dd, Dd, Dd, Dd);
    wcvt<<<dim3(64, 64, 3), tb>>>(Wo, W1, W2, WoTh, W1Th, W2Th,
        Dd, Dd, Dd, DFF, DFF, Dd);
    ln_kernel<<<MR, 256>>>(x, g1, be1, h1);
    // fused QKV -> Q,K head layout + V head layout
    hgemm<0><<<dim3(12, 64), 256, DENSE_SMEM>>>(h1, Wqkvh, bqkv, nullptr, nullptr, QKh, Dd, 3*Dd);
    vtrans<<<dim3(8, Bb*Hh), tb>>>(Vh, VTh);
    // fused attention: scores + edge bias + mask + softmax + P@V
    const __half* Qp = QKh;
    const __half* Kp = QKh + (size_t)MR * Dd;
    attn_fused<<<dim3(4, Bb*Hh), 256, FA_SMEM>>>(Qp, Kp, VTh, eb, adj, mask, O);
    // output projection + residual -> x1 (fp32)
    hgemm<1><<<dim3(4, 64), 256, DENSE_SMEM>>>(O, WoTh, bo, x, nullptr, x1, Dd, Dd);
    ln_kernel<<<MR, 256>>>(x1, g2, be2, h2);
    // FFN1 + exact gelu -> mid (half)
    hgemm<2><<<dim3(16, 64), 256, DENSE_SMEM>>>(h2, W1Th, b1, nullptr, nullptr, mid, Dd, DFF);
    // FFN2 + residual + final mask -> out (fp32)
    hgemm<3><<<dim3(4, 64), 256, DENSE_SMEM>>>(mid, W2Th, b2, x1, mask, out, DFF, Dd);
}

// round 7
// speedup vs baseline: 2.4044x; 1.0544x over previous
#include <cuda_runtime.h>
#include <cuda_fp16.h>
#include <math.h>
#include <stdint.h>

#define Bb   16
#define Nn   512
#define Dd   512
#define Hh   8
#define HDm  64
#define MR   (Bb*Nn)
#define DFF  2048

// ---------------- scratch (static device globals) ----------------
__device__ __half g_h1 [MR*Dd];
__device__ __half g_QKh[2*MR*Dd];     // [2][B][H][N][HD]
__device__ __half g_Vh [MR*Dd];       // [B][H][N][HD]
__device__ __half g_VTh[MR*Dd];       // [B][H][HD][N]
__device__ __half g_O  [MR*Dd];       // (B,N,D) half
__device__ float  g_x1 [MR*Dd];
__device__ __half g_h2 [MR*Dd];
__device__ __half g_mid[MR*DFF];
__device__ __half g_Wqkvh[3*Dd*Dd];   // [1536][512] K-major
__device__ __half g_WoTh [Dd*Dd];
__device__ __half g_W1Th [DFF*Dd];
__device__ __half g_W2Th [Dd*DFF];
__device__ float  g_bqkv[3*Dd];
__device__ uint8_t g_adjm[(size_t)Bb*Nn*Nn];  // adj*8 or 40 (masked)
__device__ int    g_adj_is32;

// ======================= helpers =======================
__device__ __forceinline__ uint32_t smem_u32(const void* p) {
    uint32_t a;
    asm("{ .reg .u64 t; cvta.to.shared.u64 t, %1; cvt.u32.u64 %0, t; }" : "=r"(a) : "l"(p));
    return a;
}
__device__ __forceinline__ void cp16h(void* s, const __half* g) {
    uint32_t sa = smem_u32(s);
    asm volatile("cp.async.cg.shared.global [%0], [%1], 16;" :: "r"(sa), "l"(g) : "memory");
}
#define CP_COMMIT() asm volatile("cp.async.commit_group;" ::: "memory")
#define CP_WAIT(n)  asm volatile("cp.async.wait_group %0;" :: "n"(n) : "memory")

__device__ __forceinline__ int swz3(int r) {          // bit-reverse of r&7
    return ((r & 1) << 2) | (r & 2) | ((r & 4) >> 2);
}
__device__ __forceinline__ uint32_t h2u(float a, float b) {
    __half2 v = __floats2half2_rn(a, b);
    return *reinterpret_cast<uint32_t*>(&v);
}

// m16n8k16 fp16 mma, f32 accum, row.col
__device__ __forceinline__ void mma16(float* c, uint32_t a0, uint32_t a1, uint32_t a2,
                                      uint32_t a3, uint32_t b0, uint32_t b1) {
    asm volatile("mma.sync.aligned.m16n8k16.row.col.f32.f16.f16.f32 "
        "{%0,%1,%2,%3},{%4,%5,%6,%7},{%8,%9},{%0,%1,%2,%3};"
        : "+f"(c[0]), "+f"(c[1]), "+f"(c[2]), "+f"(c[3])
        : "r"(a0), "r"(a1), "r"(a2), "r"(a3), "r"(b0), "r"(b1));
}

// warp 32x64 tile compute over one 64-k plane pair
__device__ __forceinline__ void plane_mma(const char* pa, const char* pb,
                                          float acc[2][8][4], int lq, int lr, int sl)
{
    #pragma unroll
    for (int sc = 0; sc < 2; sc++) {
        int go = ((sc * 4 + lr) ^ sl) << 4;
        uint4 Ar[2][2];
        #pragma unroll
        for (int mt = 0; mt < 2; mt++) {
            Ar[mt][0] = *reinterpret_cast<const uint4*>(pa + (mt*16 + lq    ) * 128 + go);
            Ar[mt][1] = *reinterpret_cast<const uint4*>(pa + (mt*16 + lq + 8) * 128 + go);
        }
        #pragma unroll
        for (int nt = 0; nt < 8; nt++) {
            uint4 Bv = *reinterpret_cast<const uint4*>(pb + (nt*8 + lq) * 128 + go);
            mma16(acc[0][nt], Ar[0][0].x, Ar[0][1].x, Ar[0][0].y, Ar[0][1].y, Bv.x, Bv.y);
            mma16(acc[1][nt], Ar[1][0].x, Ar[1][1].x, Ar[1][0].y, Ar[1][1].y, Bv.x, Bv.y);
            mma16(acc[0][nt], Ar[0][0].z, Ar[0][1].z, Ar[0][0].w, Ar[0][1].w, Bv.z, Bv.w);
            mma16(acc[1][nt], Ar[1][0].z, Ar[1][1].z, Ar[1][0].w, Ar[1][1].w, Bv.z, Bv.w);
        }
    }
}

// ======================= dense GEMM =========================
#define DENSE_SMEM 65536

template<int MODE>
__global__ void __launch_bounds__(256, 2) hgemm(
    const __half* __restrict__ A, const __half* __restrict__ Wt,
    const float* __restrict__ bias, const float* __restrict__ res,
    const float* __restrict__ mask, void* Cv, int K, int ncols)
{
    extern __shared__ char sm[];
    const int tid = threadIdx.x, lane = tid & 31, warp = tid >> 5;
    const int wm = warp >> 1, wn = warp & 1, lq = lane >> 2, lr = lane & 3;
    const int bm = blockIdx.y * 128, bn = blockIdx.x * 128;
    const int sl = swz3(lq);

    float acc[2][8][4];
    #pragma unroll
    for (int i = 0; i < 2; i++)
        #pragma unroll
        for (int j = 0; j < 8; j++)
            #pragma unroll
            for (int l = 0; l < 4; l++) acc[i][j][l] = 0.0f;

    const int NC = K >> 6;

    auto loadc = [&](int c, int buf) {
        char* dA = sm + buf * 32768;
        char* dB = dA + 16384;
        int k0 = c << 6;
        #pragma unroll
        for (int i = 0; i < 4; i++) {
            int idx = tid + i * 256, row = idx >> 3, g = idx & 7;
            int gp = ((g ^ swz3(row & 7)) << 4);
            cp16h(dA + row * 128 + gp, A  + (size_t)(bm + row) * K + k0 + g * 8);
            cp16h(dB + row * 128 + gp, Wt + (size_t)(bn + row) * K + k0 + g * 8);
        }
    };
    loadc(0, 0); CP_COMMIT();
    loadc(1, 1); CP_COMMIT();

    for (int c = 0; c < NC; c++) {
        CP_WAIT(1);
        __syncthreads();
        const char* pa = sm + (c & 1) * 32768 + (wm * 32) * 128;
        const char* pb = sm + (c & 1) * 32768 + 16384 + (wn * 64) * 128;
        plane_mma(pa, pb, acc, lq, lr, sl);
        __syncthreads();
        if (c + 2 < NC) loadc(c + 2, c & 1);
        CP_COMMIT();
    }

    #pragma unroll
    for (int mt = 0; mt < 2; mt++) {
        #pragma unroll
        for (int hf = 0; hf < 2; hf++) {
            int r = bm + wm*32 + mt*16 + lq + hf*8;
            float mr = (MODE == 3) ? mask[r] : 0.0f;
            #pragma unroll
            for (int nt = 0; nt < 8; nt++) {
                int cg = bn + wn*64 + nt*8 + 2*lr;
                float v0 = acc[mt][nt][hf*2 + 0] + bias[cg];
                float v1 = acc[mt][nt][hf*2 + 1] + bias[cg + 1];
                if (MODE == 0) {
                    int mat = cg >> 9, cc = cg & 511, hh = cc >> 6, d0 = cc & 63;
                    int b = r >> 9, n = r & 511;
                    if (mat == 0) { v0 *= 0.125f; v1 *= 0.125f; }  // pre-scale Q
                    __half2 hv = __floats2half2_rn(v0, v1);
                    if (mat < 2) {
                        __half* op = (__half*)Cv + ((((size_t)mat*Bb + b)*Hh + hh)*Nn + n)*HDm + d0;
                        *reinterpret_cast<__half2*>(op) = hv;
                    } else {
                        __half* vp = g_Vh + (((size_t)b*Hh + hh)*Nn + n)*HDm + d0;
                        *reinterpret_cast<__half2*>(vp) = hv;
                    }
                } else if (MODE == 1) {
                    float* C = (float*)Cv;
                    const float* rp = res + (size_t)r * ncols + cg;
                    float2 r2 = *reinterpret_cast<const float2*>(rp);
                    float2 o; o.x = v0 + r2.x; o.y = v1 + r2.y;
                    *reinterpret_cast<float2*>(C + (size_t)r * ncols + cg) = o;
                } else if (MODE == 2) {
                    __half* C = (__half*)Cv;
                    float o0 = 0.5f * v0 * (1.0f + erff(v0 * 0.70710678118654752f));
                    float o1 = 0.5f * v1 * (1.0f + erff(v1 * 0.70710678118654752f));
                    *reinterpret_cast<__half2*>(C + (size_t)r * ncols + cg) = __floats2half2_rn(o0, o1);
                } else {
                    float* C = (float*)Cv;
                    const float* rp = res + (size_t)r * ncols + cg;
                    float2 r2 = *reinterpret_cast<const float2*>(rp);
                    float2 o; o.x = (v0 + r2.x) * mr; o.y = (v1 + r2.y) * mr;
                    *reinterpret_cast<float2*>(C + (size_t)r * ncols + cg) = o;
                }
            }
        }
    }
}

// ======================= fused attention ====================
// adjm holds adj*8 (0..32) or 40 (masked); LUT[48]: ebias | -60000.
#define FA_SMEM 49408

__global__ void __launch_bounds__(256, 2) attn_fused(
    const __half* __restrict__ Q, const __half* __restrict__ Kh,
    const __half* __restrict__ VT, const float* __restrict__ ebias,
    const uint8_t* __restrict__ adjm, __half* __restrict__ O)
{
    extern __shared__ char sm[];
    char*  Qs  = sm;                          // 128 rows x 128B
    char*  Ks  = sm + 16384;                  // 2 x 64 rows x 128B
    char*  Vs  = sm + 32768;                  // 2 x 64 rows x 128B
    float* lut = (float*)(sm + 49152);        // 48 floats

    const int tid = threadIdx.x, lane = tid & 31, w = tid >> 5;
    const int lq = lane >> 2, lr = lane & 3;
    const int bh = blockIdx.y, b = bh >> 3, h = bh & 7;
    const int qt = blockIdx.x * 128;
    const int sl = swz3(lq);

    #pragma unroll
    for (int i = 0; i < 4; i++) {
        int idx = tid + i * 256, row = idx >> 3, g = idx & 7;
        cp16h(Qs + row * 128 + ((g ^ swz3(row & 7)) << 4),
              Q + ((size_t)bh * Nn + qt + row) * HDm + g * 8);
    }
    #pragma unroll
    for (int i = 0; i < 2; i++) {
        int idx = tid + i * 256, row = idx >> 3, g = idx & 7;
        int gp = ((g ^ swz3(row & 7)) << 4);
        cp16h(Ks + row * 128 + gp, Kh + ((size_t)bh * Nn + row) * HDm + g * 8);
        cp16h(Vs + row * 128 + gp, VT + ((size_t)bh * HDm + row) * Nn + g * 8);
    }
    if (tid < 48) lut[tid] = (tid < 40) ? ebias[tid] : -60000.0f;
    CP_COMMIT();
    #pragma unroll
    for (int i = 0; i < 2; i++) {
        int idx = tid + i * 256, row = idx >> 3, g = idx & 7;
        int gp = ((g ^ swz3(row & 7)) << 4);
        cp16h(Ks + 8192 + row * 128 + gp, Kh + ((size_t)bh * Nn + 64 + row) * HDm + g * 8);
        cp16h(Vs + 8192 + row * 128 + gp, VT + ((size_t)bh * HDm + row) * Nn + 64 + g * 8);
    }
    CP_COMMIT();

    float Oa[8][4];
    #pragma unroll
    for (int i = 0; i < 8; i++)
        #pragma unroll
        for (int j = 0; j < 4; j++) Oa[i][j] = 0.0f;
    float m0 = -1e30f, m1 = -1e30f, l0 = 0.0f, l1 = 0.0f;

    const int q0 = qt + w * 16 + lq;
    const uint8_t* am0 = adjm + ((size_t)b * Nn + q0) * Nn;
    const uint8_t* am1 = am0 + (size_t)8 * Nn;

    for (int t = 0; t < 8; t++) {
        CP_WAIT(1);
        __syncthreads();
        const char* Kb = Ks + (t & 1) * 8192;
        const char* Vb = Vs + (t & 1) * 8192;

        // ---- score mma ----
        float Sa[8][4];
        #pragma unroll
        for (int i = 0; i < 8; i++)
            #pragma unroll
            for (int j = 0; j < 4; j++) Sa[i][j] = 0.0f;
        #pragma unroll
        for (int sc = 0; sc < 2; sc++) {
            int go = ((sc * 4 + lr) ^ sl) << 4;
            uint4 A0 = *reinterpret_cast<const uint4*>(Qs + (w*16 + lq    ) * 128 + go);
            uint4 A1 = *reinterpret_cast<const uint4*>(Qs + (w*16 + lq + 8) * 128 + go);
            #pragma unroll
            for (int nt = 0; nt < 8; nt++) {
                uint4 Bv = *reinterpret_cast<const uint4*>(Kb + (nt*8 + lq) * 128 + go);
                mma16(Sa[nt], A0.x, A1.x, A0.y, A1.y, Bv.x, Bv.y);
                mma16(Sa[nt], A0.z, A1.z, A0.w, A1.w, Bv.z, Bv.w);
            }
        }

        // ---- edge bias + mask via packed table ----
        int kbase = t * 64;
        #pragma unroll
        for (int nt = 0; nt < 8; nt++) {
            int kc = kbase + nt * 8 + 2 * lr;
            uchar2 e0 = *reinterpret_cast<const uchar2*>(am0 + kc);
            uchar2 e1 = *reinterpret_cast<const uchar2*>(am1 + kc);
            Sa[nt][0] += lut[e0.x + h];
            Sa[nt][1] += lut[e0.y + h];
            Sa[nt][2] += lut[e1.x + h];
            Sa[nt][3] += lut[e1.y + h];
        }

        // ---- online softmax ----
        float tm0 = -1e30f, tm1 = -1e30f;
        #pragma unroll
        for (int nt = 0; nt < 8; nt++) {
            tm0 = fmaxf(tm0, fmaxf(Sa[nt][0], Sa[nt][1]));
            tm1 = fmaxf(tm1, fmaxf(Sa[nt][2], Sa[nt][3]));
        }
        tm0 = fmaxf(tm0, __shfl_xor_sync(0xffffffffu, tm0, 1));
        tm0 = fmaxf(tm0, __shfl_xor_sync(0xffffffffu, tm0, 2));
        tm1 = fmaxf(tm1, __shfl_xor_sync(0xffffffffu, tm1, 1));
        tm1 = fmaxf(tm1, __shfl_xor_sync(0xffffffffu, tm1, 2));
        float nm0 = fmaxf(m0, tm0), nm1 = fmaxf(m1, tm1);
        float c0 = expf(m0 - nm0), c1 = expf(m1 - nm1);
        float rs0 = 0.0f, rs1 = 0.0f;
        #pragma unroll
        for (int nt = 0; nt < 8; nt++) {
            Sa[nt][0] = expf(Sa[nt][0] - nm0); rs0 += Sa[nt][0];
            Sa[nt][1] = expf(Sa[nt][1] - nm0); rs0 += Sa[nt][1];
            Sa[nt][2] = expf(Sa[nt][2] - nm1); rs1 += Sa[nt][2];
            Sa[nt][3] = expf(Sa[nt][3] - nm1); rs1 += Sa[nt][3];
        }
        rs0 += __shfl_xor_sync(0xffffffffu, rs0, 1);
        rs0 += __shfl_xor_sync(0xffffffffu, rs0, 2);
        rs1 += __shfl_xor_sync(0xffffffffu, rs1, 1);
        rs1 += __shfl_xor_sync(0xffffffffu, rs1, 2);
        l0 = l0 * c0 + rs0; l1 = l1 * c1 + rs1;
        m0 = nm0; m1 = nm1;
        #pragma unroll
        for (int nt = 0; nt < 8; nt++) {
            Oa[nt][0] *= c0; Oa[nt][1] *= c0;
            Oa[nt][2] *= c1; Oa[nt][3] *= c1;
        }

        uint32_t ph[8][2];
        #pragma unroll
        for (int nt = 0; nt < 8; nt++) {
            ph[nt][0] = h2u(Sa[nt][0], Sa[nt][1]);
            ph[nt][1] = h2u(Sa[nt][2], Sa[nt][3]);
        }

        // ---- PV mma ----
        #pragma unroll
        for (int kf = 0; kf < 4; kf++) {
            uint32_t a0 = ph[2*kf][0],   a1 = ph[2*kf][1];
            uint32_t a2 = ph[2*kf+1][0], a3 = ph[2*kf+1][1];
            int g0 = (((2*kf)     ^ sl) << 4) + lr * 4;
            int g1 = (((2*kf + 1) ^ sl) << 4) + lr * 4;
            #pragma unroll
            for (int nt = 0; nt < 8; nt++) {
                const char* vr = Vb + (nt*8 + lq) * 128;
                uint32_t b0 = *reinterpret_cast<const uint32_t*>(vr + g0);
                uint32_t b1 = *reinterpret_cast<const uint32_t*>(vr + g1);
                mma16(Oa[nt], a0, a1, a2, a3, b0, b1);
            }
        }

        __syncthreads();
        if (t + 2 < 8) {
            int kt2 = (t + 2) * 64;
            char* dK = Ks + (t & 1) * 8192;
            char* dV = Vs + (t & 1) * 8192;
            #pragma unroll
            for (int i = 0; i < 2; i++) {
                int idx = tid + i * 256, row = idx >> 3, g = idx & 7;
                int gp = ((g ^ swz3(row & 7)) << 4);
                cp16h(dK + row * 128 + gp, Kh + ((size_t)bh * Nn + kt2 + row) * HDm + g * 8);
                cp16h(dV + row * 128 + gp, VT + ((size_t)bh * HDm + row) * Nn + kt2 + g * 8);
            }
        }
        CP_COMMIT();
    }

    float inv0 = (m0 > -5.0e4f) ? (1.0f / l0) : 0.0f;
    float inv1 = (m1 > -5.0e4f) ? (1.0f / l1) : 0.0f;
    __half* o0 = O + ((size_t)(b * Nn + q0)) * Dd + h * HDm;
    __half* o1 = o0 + (size_t)8 * Dd;
    #pragma unroll
    for (int nt = 0; nt < 8; nt++) {
        int d = nt * 8 + 2 * lr;
        *reinterpret_cast<__half2*>(o0 + d) = __floats2half2_rn(Oa[nt][0] * inv0, Oa[nt][1] * inv0);
        *reinterpret_cast<__half2*>(o1 + d) = __floats2half2_rn(Oa[nt][2] * inv1, Oa[nt][3] * inv1);
    }
}

// ---------------- adj pack: adjm = mask ? adj*8 : 40 ----------------
__global__ void adj_pack(const int* __restrict__ adj32, const float* __restrict__ mask,
                         uint8_t* __restrict__ out)
{
    const int is32 = g_adj_is32;
    int base = (blockIdx.x * 256 + threadIdx.x) * 8;
    int b = base >> 18;
    int rem = base & (Nn * Nn - 1);
    int q = rem >> 9;
    float mq = mask[b * Nn + q];
    const float* mkp = mask + b * Nn;
    int k0 = rem & 511;
    uchar4 o[2];
    #pragma unroll
    for (int e = 0; e < 8; e++) {
        int i = base + e;
        int t = is32 ? adj32[i] : adj32[2 * i];
        float mk = mkp[k0 + e];
        uint8_t v = (mq * mk == 0.0f) ? (uint8_t)40 : (uint8_t)(t << 3);
        ((uint8_t*)o)[e] = v;
    }
    *reinterpret_cast<uchar4*>(out + base)     = o[0];
    *reinterpret_cast<uchar4*>(out + base + 4) = o[1];
}

// ---------------- V transpose per (b,h) ----------------
__global__ void vtrans(const __half* __restrict__ V, __half* __restrict__ VT)
{
    __shared__ __half t[64][65];
    int bh = blockIdx.y, nb = blockIdx.x * 64;
    int tx = threadIdx.x, ty = threadIdx.y;
    const __half2* src = reinterpret_cast<const __half2*>(V + ((size_t)bh*Nn + nb) * HDm);
    #pragma unroll
    for (int i = 0; i < 8; i++) {
        int n = ty + i * 8;
        __half2 v = src[n * 32 + tx];
        t[n][2*tx] = __low2half(v); t[n][2*tx+1] = __high2half(v);
    }
    __syncthreads();
    __half2* dst = reinterpret_cast<__half2*>(VT + (size_t)bh * HDm * Nn);
    #pragma unroll
    for (int i = 0; i < 8; i++) {
        int d = ty + i * 8;
        __half2 o = __halves2half2(t[2*tx][d], t[2*tx+1][d]);
        dst[(d * Nn + nb + 2*tx) >> 1] = o;
    }
}

// ---------------- weight convert (all 6): out[n][k] = half(in[k][n]) ------------
__global__ void wcvt6(const float* __restrict__ Wq, const float* __restrict__ Wk,
                      const float* __restrict__ Wv, const float* __restrict__ Wo,
                      const float* __restrict__ W1, const float* __restrict__ W2,
                      __half* __restrict__ dqkv, __half* __restrict__ dwo,
                      __half* __restrict__ dw1, __half* __restrict__ dw2)
{
    int z = blockIdx.z;
    const float* in; __half* out; int K, N;
    switch (z) {
        case 0: in = Wq; out = dqkv;                     K = Dd;  N = Dd;  break;
        case 1: in = Wk; out = dqkv + (size_t)Dd*Dd;     K = Dd;  N = Dd;  break;
        case 2: in = Wv; out = dqkv + (size_t)2*Dd*Dd;   K = Dd;  N = Dd;  break;
        case 3: in = Wo; out = dwo;                      K = Dd;  N = Dd;  break;
        case 4: in = W1; out = dw1;                      K = Dd;  N = DFF; break;
        default: in = W2; out = dw2;                     K = DFF; N = Dd;  break;
    }
    int bx = blockIdx.x * 32, by = blockIdx.y * 32;
    if (bx >= N || by >= K) return;
    __shared__ float t[32][33];
    int tx = threadIdx.x, ty = threadIdx.y;
    #pragma unroll
    for (int i = 0; i < 32; i += 8)
        t[ty + i][tx] = in[(size_t)(by + ty + i) * N + bx + tx];
    __syncthreads();
    #pragma unroll
    for (int i = 0; i < 32; i += 8)
        out[(size_t)(bx + ty + i) * K + by + tx] = __float2half_rn(t[tx][ty + i]);
}

// ---------------- prep: adj dtype detect + bias concat ----------------
__global__ void prep_kernel(const int* __restrict__ a,
                            const float* __restrict__ bq, const float* __restrict__ bk,
                            const float* __restrict__ bv, float* __restrict__ o)
{
    if (blockIdx.x == 0) {
        __shared__ int flag;
        if (threadIdx.x == 0) flag = 0;
        __syncthreads();
        for (int i = threadIdx.x; i < 8192; i += blockDim.x)
            if (a[2*i + 1] != 0) flag = 1;
        __syncthreads();
        if (threadIdx.x == 0) g_adj_is32 = flag;
    } else {
        int i = (blockIdx.x - 1) * 256 + threadIdx.x;
        if (i < 512) o[i] = bq[i];
        else if (i < 1024) o[i] = bk[i - 512];
        else o[i] = bv[i - 1024];
    }
}

// ---------------- LayerNorm: fp32 in, half out ----------------
__global__ __launch_bounds__(256) void ln_kernel(
    const float* __restrict__ X, const float* __restrict__ g,
    const float* __restrict__ beta, __half* __restrict__ Y)
{
    int row = blockIdx.x;
    const float* x = X + (size_t)row * Dd;
    int tid = threadIdx.x;
    float v0 = x[tid], v1 = x[tid + 256];

    __shared__ float red1[8], red2[8];
    float s = v0 + v1;
    #pragma unroll
    for (int o = 16; o; o >>= 1) s += __shfl_xor_sync(0xffffffffu, s, o);
    if ((tid & 31) == 0) red1[tid >> 5] = s;
    __syncthreads();
    float tot = red1[0]+red1[1]+red1[2]+red1[3]+red1[4]+red1[5]+red1[6]+red1[7];
    float mu = tot * (1.0f / 512.0f);

    float d0 = v0 - mu, d1 = v1 - mu;
    float s2 = d0*d0 + d1*d1;
    #pragma unroll
    for (int o = 16; o; o >>= 1) s2 += __shfl_xor_sync(0xffffffffu, s2, o);
    if ((tid & 31) == 0) red2[tid >> 5] = s2;
    __syncthreads();
    float tot2 = red2[0]+red2[1]+red2[2]+red2[3]+red2[4]+red2[5]+red2[6]+red2[7];
    float inv = rsqrtf(tot2 * (1.0f / 512.0f) + 1e-5f);

    Y[(size_t)row*Dd + tid      ] = __float2half_rn(d0 * inv * g[tid      ] + beta[tid      ]);
    Y[(size_t)row*Dd + tid + 256] = __float2half_rn(d1 * inv * g[tid + 256] + beta[tid + 256]);
}

// ---------------------------------- launch ----------------------------------
extern "C" void kernel_launch(void* const* d_in, const int* in_sizes, int n_in,
                              void* d_out, int out_size)
{
    const float* x    = (const float*)d_in[0];
    const int*   adj  = (const int*)  d_in[1];
    const float* mask = (const float*)d_in[2];
    const float* Wq   = (const float*)d_in[3];
    const float* bq   = (const float*)d_in[4];
    const float* Wk   = (const float*)d_in[5];
    const float* bk   = (const float*)d_in[6];
    const float* Wv   = (const float*)d_in[7];
    const float* bv   = (const float*)d_in[8];
    const float* Wo   = (const float*)d_in[9];
    const float* bo   = (const float*)d_in[10];
    const float* eb   = (const float*)d_in[11];
    const float* W1   = (const float*)d_in[12];
    const float* b1   = (const float*)d_in[13];
    const float* W2   = (const float*)d_in[14];
    const float* b2   = (const float*)d_in[15];
    const float* g1   = (const float*)d_in[16];
    const float* be1  = (const float*)d_in[17];
    const float* g2   = (const float*)d_in[18];
    const float* be2  = (const float*)d_in[19];
    float* out = (float*)d_out;

    __half *h1, *QKh, *Vh, *VTh, *O, *h2, *mid;
    __half *Wqkvh, *WoTh, *W1Th, *W2Th;
    float *x1, *bqkv;
    uint8_t* adjm;
    cudaGetSymbolAddress((void**)&h1,   g_h1);
    cudaGetSymbolAddress((void**)&QKh,  g_QKh);
    cudaGetSymbolAddress((void**)&Vh,   g_Vh);
    cudaGetSymbolAddress((void**)&VTh,  g_VTh);
    cudaGetSymbolAddress((void**)&O,    g_O);
    cudaGetSymbolAddress((void**)&x1,   g_x1);
    cudaGetSymbolAddress((void**)&h2,   g_h2);
    cudaGetSymbolAddress((void**)&mid,  g_mid);
    cudaGetSymbolAddress((void**)&Wqkvh,g_Wqkvh);
    cudaGetSymbolAddress((void**)&WoTh, g_WoTh);
    cudaGetSymbolAddress((void**)&W1Th, g_W1Th);
    cudaGetSymbolAddress((void**)&W2Th, g_W2Th);
    cudaGetSymbolAddress((void**)&bqkv, g_bqkv);
    cudaGetSymbolAddress((void**)&adjm, g_adjm);

    static int attr_set = 0;
    if (!attr_set) {
        cudaFuncSetAttribute(hgemm<0>, cudaFuncAttributeMaxDynamicSharedMemorySize, DENSE_SMEM);
        cudaFuncSetAttribute(hgemm<1>, cudaFuncAttributeMaxDynamicSharedMemorySize, DENSE_SMEM);
        cudaFuncSetAttribute(hgemm<2>, cudaFuncAttributeMaxDynamicSharedMemorySize, DENSE_SMEM);
        cudaFuncSetAttribute(hgemm<3>, cudaFuncAttributeMaxDynamicSharedMemorySize, DENSE_SMEM);
        cudaFuncSetAttribute(attn_fused, cudaFuncAttributeMaxDynamicSharedMemorySize, FA_SMEM);
        attr_set = 1;
    }

    dim3 tb(32, 8);
    // 0: prep (detect + bias concat)
    prep_kernel<<<7, 256>>>(adj, bq, bk, bv, bqkv);
    // 1: all weight converts
    wcvt6<<<dim3(64, 64, 6), tb>>>(Wq, Wk, Wv, Wo, W1, W2, Wqkvh, WoTh, W1Th, W2Th);
    // 2: LN1
    ln_kernel<<<MR, 256>>>(x, g1, be1, h1);
    // 3: fused QKV (profiled at capture index 3)
    hgemm<0><<<dim3(12, 64), 256, DENSE_SMEM>>>(h1, Wqkvh, bqkv, nullptr, nullptr, QKh, Dd, 3*Dd);
    // 4: adj pack
    adj_pack<<<(Bb*Nn*Nn)/(256*8), 256>>>(adj, mask, adjm);
    // 5: V transpose
    vtrans<<<dim3(8, Bb*Hh), tb>>>(Vh, VTh);
    // 6: fused attention
    const __half* Qp = QKh;
    const __half* Kp = QKh + (size_t)MR * Dd;
    attn_fused<<<dim3(4, Bb*Hh), 256, FA_SMEM>>>(Qp, Kp, VTh, eb, adjm, O);
    // 7: output projection + residual
    hgemm<1><<<dim3(4, 64), 256, DENSE_SMEM>>>(O, WoTh, bo, x, nullptr, x1, Dd, Dd);
    // 8: LN2
    ln_kernel<<<MR, 256>>>(x1, g2, be2, h2);
    // 9: FFN1 + gelu
    hgemm<2><<<dim3(16, 64), 256, DENSE_SMEM>>>(h2, W1Th, b1, nullptr, nullptr, mid, Dd, DFF);
    // 10: FFN2 + residual + mask
    hgemm<3><<<dim3(4, 64), 256, DENSE_SMEM>>>(mid, W2Th, b2, x1, mask, out, DFF, Dd);
}